// round 5
// baseline (speedup 1.0000x reference)
#include <cuda_runtime.h>
#include <mma.h>
#include <cstdint>

using namespace nvcuda;

#define NN 100000
#define NN_PAD 100096   // 782 * 128
#define MAXE 3300000
#define SCAN_BS 512

// ---------------- scratch (static device globals) ---------------------------
__device__ __align__(256) int   g_indeg[NN];
__device__ __align__(256) int   g_outdeg[NN];
__device__ __align__(256) int   g_fill[NN];
__device__ __align__(256) int   g_rowptr[NN + 1];
__device__ __align__(256) int   g_blocksums[256];
__device__ __align__(256) int   g_esrc[MAXE];
__device__ __align__(256) float g_snorm[NN];
__device__ __align__(256) float g_dnorm[NN];
__device__ __align__(256) float g_agg[(size_t)NN_PAD * 256];  // layer-1 output
__device__ __align__(256) float g_h[(size_t)NN_PAD * 256];    // layer-0 output
__device__ __align__(256) float g_xm[(size_t)NN_PAD * 64];

// ---------------- degrees / norms -------------------------------------------
__global__ void zero_init_kernel() {
    int i = blockIdx.x * blockDim.x + threadIdx.x;
    if (i < NN) { g_indeg[i] = 0; g_outdeg[i] = 0; g_fill[i] = 0; }
}

__global__ void degree_kernel(const int* __restrict__ src,
                              const int* __restrict__ dst, int nE) {
    int i = blockIdx.x * blockDim.x + threadIdx.x;
    if (i < nE) {
        atomicAdd(&g_outdeg[src[i]], 1);
        atomicAdd(&g_indeg[dst[i]], 1);
    }
}

__global__ void norm_kernel() {
    int i = blockIdx.x * blockDim.x + threadIdx.x;
    if (i < NN) {
        g_snorm[i] = rsqrtf(fmaxf((float)g_outdeg[i], 1.f));
        g_dnorm[i] = rsqrtf(fmaxf((float)g_indeg[i], 1.f));
    }
}

// ---------------- CSR build: scan + bucket fill ------------------------------
__global__ void scan1_kernel() {
    __shared__ int sh[SCAN_BS];
    int i = blockIdx.x * SCAN_BS + threadIdx.x;
    int v = (i < NN) ? g_indeg[i] : 0;
    sh[threadIdx.x] = v;
    __syncthreads();
    for (int off = 1; off < SCAN_BS; off <<= 1) {
        int t = (threadIdx.x >= off) ? sh[threadIdx.x - off] : 0;
        __syncthreads();
        sh[threadIdx.x] += t;
        __syncthreads();
    }
    if (i < NN) g_rowptr[i] = sh[threadIdx.x] - v;
    if (threadIdx.x == SCAN_BS - 1) g_blocksums[blockIdx.x] = sh[threadIdx.x];
}

__global__ void scan2_kernel(int nb) {
    __shared__ int sh[256];
    int t = threadIdx.x;
    int v = (t < nb) ? g_blocksums[t] : 0;
    sh[t] = v;
    __syncthreads();
    for (int off = 1; off < 256; off <<= 1) {
        int u = (t >= off) ? sh[t - off] : 0;
        __syncthreads();
        sh[t] += u;
        __syncthreads();
    }
    if (t < nb) g_blocksums[t] = sh[t] - v;
}

__global__ void scan3_kernel(int nE) {
    int i = blockIdx.x * SCAN_BS + threadIdx.x;
    if (i < NN) g_rowptr[i] += g_blocksums[blockIdx.x];
    if (i == 0) g_rowptr[NN] = nE;
}

__global__ void fillcsr_kernel(const int* __restrict__ src,
                               const int* __restrict__ dst, int nE) {
    int i = blockIdx.x * blockDim.x + threadIdx.x;
    if (i < nE) {
        int d = dst[i];
        int pos = g_rowptr[d] + atomicAdd(&g_fill[d], 1);
        g_esrc[pos] = src[i];
    }
}

// ---------------- fused layer: gather256 -> tf32 GEMM(K=256,N=256) -----------
// CTA = 128 dst rows. Phase 1: 8 warps gather 16 rows each into smem As
// (fp32 accum, *dnorm, tf32 convert once). Phase 2: GEMM from smem, W tiles
// (32 x 256) double-buffered, warp tile 64x64 (4x4 WMMA m16n16k8), ReLU, store.
#define AST 268   // smem row stride in floats (268 mod 32 = 12 -> conflict-free)
__global__ __launch_bounds__(256, 1) void fused_layer_kernel(
    const float* __restrict__ x, const float* __restrict__ W,
    float* __restrict__ out, bool relu) {
    extern __shared__ float smem[];
    float* As = smem;                       // [128][AST]
    float* Bs0 = smem + 128 * AST;          // [32][AST]
    float* Bs1 = Bs0 + 32 * AST;

    const int t = threadIdx.x;
    const int warp = t >> 5;
    const int lane = t & 31;
    const int row0 = blockIdx.x * 128;

    // ---------- phase 1: gather ----------
    for (int rr = 0; rr < 16; rr++) {
        int rloc = warp * 16 + rr;
        int v = row0 + rloc;
        float4 acc0 = make_float4(0.f, 0.f, 0.f, 0.f);
        float4 acc1 = make_float4(0.f, 0.f, 0.f, 0.f);
        float dn = 0.f;
        if (v < NN) {
            dn = __ldg(&g_dnorm[v]);
            int row = g_rowptr[v];
            int end = g_rowptr[v + 1];
            for (int base = row; base < end; base += 32) {
                int n = min(32, end - base);
                int s = 0;
                float w = 0.f;
                if (lane < n) { s = __ldg(&g_esrc[base + lane]); w = __ldg(&g_snorm[s]); }
                int k = 0;
                for (; k + 2 <= n; k += 2) {
                    int s0 = __shfl_sync(0xffffffffu, s, k);
                    int s1 = __shfl_sync(0xffffffffu, s, k + 1);
                    float w0 = __shfl_sync(0xffffffffu, w, k);
                    float w1 = __shfl_sync(0xffffffffu, w, k + 1);
                    const float4* r0 = (const float4*)(x + (size_t)s0 * 256);
                    const float4* r1 = (const float4*)(x + (size_t)s1 * 256);
                    float4 a0 = __ldg(&r0[lane]);
                    float4 b0 = __ldg(&r0[lane + 32]);
                    float4 a1 = __ldg(&r1[lane]);
                    float4 b1 = __ldg(&r1[lane + 32]);
                    acc0.x = fmaf(w0, a0.x, fmaf(w1, a1.x, acc0.x));
                    acc0.y = fmaf(w0, a0.y, fmaf(w1, a1.y, acc0.y));
                    acc0.z = fmaf(w0, a0.z, fmaf(w1, a1.z, acc0.z));
                    acc0.w = fmaf(w0, a0.w, fmaf(w1, a1.w, acc0.w));
                    acc1.x = fmaf(w0, b0.x, fmaf(w1, b1.x, acc1.x));
                    acc1.y = fmaf(w0, b0.y, fmaf(w1, b1.y, acc1.y));
                    acc1.z = fmaf(w0, b0.z, fmaf(w1, b1.z, acc1.z));
                    acc1.w = fmaf(w0, b0.w, fmaf(w1, b1.w, acc1.w));
                }
                if (k < n) {
                    int s0 = __shfl_sync(0xffffffffu, s, k);
                    float w0 = __shfl_sync(0xffffffffu, w, k);
                    const float4* r0 = (const float4*)(x + (size_t)s0 * 256);
                    float4 a0 = __ldg(&r0[lane]);
                    float4 b0 = __ldg(&r0[lane + 32]);
                    acc0.x = fmaf(w0, a0.x, acc0.x);
                    acc0.y = fmaf(w0, a0.y, acc0.y);
                    acc0.z = fmaf(w0, a0.z, acc0.z);
                    acc0.w = fmaf(w0, a0.w, acc0.w);
                    acc1.x = fmaf(w0, b0.x, acc1.x);
                    acc1.y = fmaf(w0, b0.y, acc1.y);
                    acc1.z = fmaf(w0, b0.z, acc1.z);
                    acc1.w = fmaf(w0, b0.w, acc1.w);
                }
            }
        }
        float* ar = As + (size_t)rloc * AST;
        ar[lane * 4 + 0] = wmma::__float_to_tf32(acc0.x * dn);
        ar[lane * 4 + 1] = wmma::__float_to_tf32(acc0.y * dn);
        ar[lane * 4 + 2] = wmma::__float_to_tf32(acc0.z * dn);
        ar[lane * 4 + 3] = wmma::__float_to_tf32(acc0.w * dn);
        ar[128 + lane * 4 + 0] = wmma::__float_to_tf32(acc1.x * dn);
        ar[128 + lane * 4 + 1] = wmma::__float_to_tf32(acc1.y * dn);
        ar[128 + lane * 4 + 2] = wmma::__float_to_tf32(acc1.z * dn);
        ar[128 + lane * 4 + 3] = wmma::__float_to_tf32(acc1.w * dn);
    }

    // ---------- phase 2: GEMM ----------
    // W tile load mapping: 32 rows x 256 cols; thread t -> row t>>3,
    // 8 float4 at cols (t&7)*32 + q*4
    const int b_row = t >> 3;
    const int b_c0 = (t & 7) * 32;
    const int wm = warp >> 2;   // 0..1 -> 64-row strip
    const int wn = warp & 3;    // 0..3 -> 64-col strip

    wmma::fragment<wmma::accumulator, 16, 16, 8, float> acc[4][4];
#pragma unroll
    for (int i = 0; i < 4; i++)
#pragma unroll
        for (int j = 0; j < 4; j++) wmma::fill_fragment(acc[i][j], 0.f);

    float4 br[8];
#pragma unroll
    for (int q = 0; q < 8; q++)
        br[q] = *(const float4*)&W[(size_t)b_row * 256 + b_c0 + q * 4];

    auto store_b = [&](float* Bs) {
        float* bp = Bs + (size_t)b_row * AST + b_c0;
#pragma unroll
        for (int q = 0; q < 8; q++) {
            bp[q * 4 + 0] = wmma::__float_to_tf32(br[q].x);
            bp[q * 4 + 1] = wmma::__float_to_tf32(br[q].y);
            bp[q * 4 + 2] = wmma::__float_to_tf32(br[q].z);
            bp[q * 4 + 3] = wmma::__float_to_tf32(br[q].w);
        }
    };

    store_b(Bs0);
    __syncthreads();   // also closes gather phase (As ready)

    for (int k0 = 0; k0 < 256; k0 += 32) {
        float* Bcur = ((k0 >> 5) & 1) ? Bs1 : Bs0;
        float* Bnext = ((k0 >> 5) & 1) ? Bs0 : Bs1;
        const bool has_next = (k0 + 32) < 256;
        if (has_next) {
#pragma unroll
            for (int q = 0; q < 8; q++)
                br[q] = *(const float4*)&W[(size_t)(k0 + 32 + b_row) * 256 + b_c0 + q * 4];
        }
#pragma unroll
        for (int kk = 0; kk < 32; kk += 8) {
            wmma::fragment<wmma::matrix_a, 16, 16, 8, wmma::precision::tf32,
                           wmma::row_major> af[4];
            wmma::fragment<wmma::matrix_b, 16, 16, 8, wmma::precision::tf32,
                           wmma::row_major> bf[4];
#pragma unroll
            for (int i = 0; i < 4; i++)
                wmma::load_matrix_sync(af[i],
                    As + (size_t)(wm * 64 + i * 16) * AST + k0 + kk, AST);
#pragma unroll
            for (int j = 0; j < 4; j++)
                wmma::load_matrix_sync(bf[j],
                    Bcur + (size_t)kk * AST + wn * 64 + j * 16, AST);
#pragma unroll
            for (int i = 0; i < 4; i++)
#pragma unroll
                for (int j = 0; j < 4; j++)
                    wmma::mma_sync(acc[i][j], af[i], bf[j], acc[i][j]);
        }
        if (has_next) {
            store_b(Bnext);
            __syncthreads();
        }
    }

#pragma unroll
    for (int i = 0; i < 4; i++)
#pragma unroll
        for (int j = 0; j < 4; j++) {
            if (relu) {
#pragma unroll
                for (int e = 0; e < acc[i][j].num_elements; e++)
                    acc[i][j].x[e] = fmaxf(acc[i][j].x[e], 0.f);
            }
            float* cptr = out + (size_t)(row0 + wm * 64 + i * 16) * 256 +
                          wn * 64 + j * 16;
            wmma::store_matrix_sync(cptr, acc[i][j], 256, wmma::mem_row_major);
        }
}

// ---------------- layer-2 GEMM (N=64): xm = (h * snorm) @ W2 -----------------
template <bool RELU>
__global__ __launch_bounds__(256, 2) void gemm_tf32_kernel(
    const float* __restrict__ A, const float* __restrict__ W,
    const float* __restrict__ norm, float* __restrict__ C, int M, int N) {
    constexpr int BM = 128, BK = 32;
    constexpr int BN = 64;
    constexpr int APAD = 8, BPAD = 8;
    __shared__ float As[BM][BK + APAD];
    __shared__ float Bs[BK][BN + BPAD];

    const int t = threadIdx.x;
    const int warp = t >> 5;
    const int wm = warp >> 1;
    const int wn = warp & 1;
    const int row0 = blockIdx.x * BM;
    const int col0 = blockIdx.y * BN;

    const int a_row = t >> 1;
    const int a_c0 = (t & 1) * 16;
    const bool a_ok = (row0 + a_row) < M;
    const float nrm = a_ok ? __ldg(&norm[row0 + a_row]) : 0.f;
    const float* Aptr = A + (size_t)(row0 + a_row) * 256 + a_c0;

    const int b_row = t >> 3;
    const int b_c0 = (t & 7) * 8;

    wmma::fragment<wmma::accumulator, 16, 16, 8, float> acc[2][2];
#pragma unroll
    for (int i = 0; i < 2; i++)
#pragma unroll
        for (int j = 0; j < 2; j++) wmma::fill_fragment(acc[i][j], 0.f);

    float4 ar[4], br[2];
#pragma unroll
    for (int q = 0; q < 4; q++) ar[q] = *(const float4*)(Aptr + q * 4);
#pragma unroll
    for (int q = 0; q < 2; q++)
        br[q] = *(const float4*)&W[(size_t)b_row * N + col0 + b_c0 + q * 4];

    auto store_tiles = [&]() {
#pragma unroll
        for (int q = 0; q < 4; q++) {
            As[a_row][a_c0 + q * 4 + 0] = wmma::__float_to_tf32(ar[q].x * nrm);
            As[a_row][a_c0 + q * 4 + 1] = wmma::__float_to_tf32(ar[q].y * nrm);
            As[a_row][a_c0 + q * 4 + 2] = wmma::__float_to_tf32(ar[q].z * nrm);
            As[a_row][a_c0 + q * 4 + 3] = wmma::__float_to_tf32(ar[q].w * nrm);
        }
#pragma unroll
        for (int q = 0; q < 2; q++) {
            Bs[b_row][b_c0 + q * 4 + 0] = wmma::__float_to_tf32(br[q].x);
            Bs[b_row][b_c0 + q * 4 + 1] = wmma::__float_to_tf32(br[q].y);
            Bs[b_row][b_c0 + q * 4 + 2] = wmma::__float_to_tf32(br[q].z);
            Bs[b_row][b_c0 + q * 4 + 3] = wmma::__float_to_tf32(br[q].w);
        }
    };

    store_tiles();
    __syncthreads();

    for (int k0 = 0; k0 < 256; k0 += BK) {
        const bool has_next = (k0 + BK) < 256;
        if (has_next) {
#pragma unroll
            for (int q = 0; q < 4; q++)
                ar[q] = *(const float4*)(Aptr + k0 + BK + q * 4);
#pragma unroll
            for (int q = 0; q < 2; q++)
                br[q] = *(const float4*)&W[(size_t)(k0 + BK + b_row) * N + col0 + b_c0 + q * 4];
        }
#pragma unroll
        for (int kk = 0; kk < BK; kk += 8) {
            wmma::fragment<wmma::matrix_a, 16, 16, 8, wmma::precision::tf32,
                           wmma::row_major> af[2];
            wmma::fragment<wmma::matrix_b, 16, 16, 8, wmma::precision::tf32,
                           wmma::row_major> bf[2];
#pragma unroll
            for (int i = 0; i < 2; i++)
                wmma::load_matrix_sync(af[i], &As[wm * 32 + i * 16][kk], BK + APAD);
#pragma unroll
            for (int j = 0; j < 2; j++)
                wmma::load_matrix_sync(bf[j], &Bs[kk][wn * 32 + j * 16], BN + BPAD);
#pragma unroll
            for (int i = 0; i < 2; i++)
#pragma unroll
                for (int j = 0; j < 2; j++)
                    wmma::mma_sync(acc[i][j], af[i], bf[j], acc[i][j]);
        }
        __syncthreads();
        if (has_next) {
            store_tiles();
            __syncthreads();
        }
    }

#pragma unroll
    for (int i = 0; i < 2; i++)
#pragma unroll
        for (int j = 0; j < 2; j++) {
            if (RELU) {
#pragma unroll
                for (int e = 0; e < acc[i][j].num_elements; e++)
                    acc[i][j].x[e] = fmaxf(acc[i][j].x[e], 0.f);
            }
            float* cptr = C + (size_t)(row0 + wm * 32 + i * 16) * N +
                          col0 + wn * 32 + j * 16;
            wmma::store_matrix_sync(cptr, acc[i][j], N, wmma::mem_row_major);
        }
}

// ---------------- gather64: out[v] = dnorm[v] * sum_e xm[src_e] --------------
__global__ __launch_bounds__(256) void gather64_kernel(
    const float* __restrict__ x, float* __restrict__ out) {
    int v = (blockIdx.x * blockDim.x + threadIdx.x) >> 5;
    int lane = threadIdx.x & 31;
    if (v >= NN) return;
    int row = g_rowptr[v];
    int end = g_rowptr[v + 1];
    float2 acc = make_float2(0.f, 0.f);
    for (int base = row; base < end; base += 32) {
        int n = min(32, end - base);
        int s = 0;
        if (lane < n) s = __ldg(&g_esrc[base + lane]);
        int k = 0;
        for (; k + 4 <= n; k += 4) {
            int s0 = __shfl_sync(0xffffffffu, s, k);
            int s1 = __shfl_sync(0xffffffffu, s, k + 1);
            int s2 = __shfl_sync(0xffffffffu, s, k + 2);
            int s3 = __shfl_sync(0xffffffffu, s, k + 3);
            float2 a0 = __ldg((const float2*)(x + (size_t)s0 * 64) + lane);
            float2 a1 = __ldg((const float2*)(x + (size_t)s1 * 64) + lane);
            float2 a2 = __ldg((const float2*)(x + (size_t)s2 * 64) + lane);
            float2 a3 = __ldg((const float2*)(x + (size_t)s3 * 64) + lane);
            acc.x += (a0.x + a1.x) + (a2.x + a3.x);
            acc.y += (a0.y + a1.y) + (a2.y + a3.y);
        }
        for (; k < n; k++) {
            int s0 = __shfl_sync(0xffffffffu, s, k);
            float2 a0 = __ldg((const float2*)(x + (size_t)s0 * 64) + lane);
            acc.x += a0.x;
            acc.y += a0.y;
        }
    }
    float w = g_dnorm[v];
    ((float2*)(out + (size_t)v * 64))[lane] = make_float2(acc.x * w, acc.y * w);
}

// ---------------- launch -----------------------------------------------------
extern "C" void kernel_launch(void* const* d_in, const int* in_sizes, int n_in,
                              void* d_out, int out_size) {
    const float* feat = (const float*)d_in[0];
    const int* src = (const int*)d_in[1];
    const int* dst = (const int*)d_in[2];
    const float* W0 = (const float*)d_in[3];
    const float* W1 = (const float*)d_in[4];
    const float* W2 = (const float*)d_in[5];
    float* out = (float*)d_out;
    const int nE = in_sizes[1];

    float *agg, *h, *xm, *snorm;
    cudaGetSymbolAddress((void**)&agg, g_agg);
    cudaGetSymbolAddress((void**)&h, g_h);
    cudaGetSymbolAddress((void**)&xm, g_xm);
    cudaGetSymbolAddress((void**)&snorm, g_snorm);

    const int T = 256;
    const int NB = (NN + SCAN_BS - 1) / SCAN_BS;      // 196
    const int n_blocks = NN_PAD / 128;                // 782
    const int gather_blocks = (NN * 32 + T - 1) / T;  // 12500

    const int FUSED_SMEM = (128 * AST + 2 * 32 * AST) * 4;  // 205,824 B
    cudaFuncSetAttribute(fused_layer_kernel,
                         cudaFuncAttributeMaxDynamicSharedMemorySize, FUSED_SMEM);

    // degrees + norms + CSR build
    zero_init_kernel<<<(NN + T - 1) / T, T>>>();
    degree_kernel<<<(nE + T - 1) / T, T>>>(src, dst, nE);
    norm_kernel<<<(NN + T - 1) / T, T>>>();
    scan1_kernel<<<NB, SCAN_BS>>>();
    scan2_kernel<<<1, 256>>>(NB);
    scan3_kernel<<<NB, SCAN_BS>>>(nE);
    fillcsr_kernel<<<(nE + T - 1) / T, T>>>(src, dst, nE);

    // layer 0: h = relu( (A^T(feat*snorm)) * dnorm @ W0 )   [fused]
    fused_layer_kernel<<<n_blocks, T, FUSED_SMEM>>>(feat, W0, h, true);
    // layer 1: agg = relu( (A^T(h*snorm)) * dnorm @ W1 )    [fused]
    fused_layer_kernel<<<n_blocks, T, FUSED_SMEM>>>(h, W1, agg, true);
    // layer 2: xm = (agg * snorm) @ W2; out = dnorm * (A^T xm)
    gemm_tf32_kernel<false><<<dim3(n_blocks, 1), T>>>(agg, W2, snorm, xm, NN, 64);
    gather64_kernel<<<gather_blocks, T>>>(xm, out);
}

// round 6
// speedup vs baseline: 1.8954x; 1.8954x over previous
#include <cuda_runtime.h>
#include <mma.h>
#include <cstdint>

using namespace nvcuda;

#define NN 100000
#define NN_PAD 100096   // 782 * 128
#define MAXE 3300000
#define SCAN_BS 512

// ---------------- scratch (static device globals) ---------------------------
__device__ __align__(256) int   g_indeg[NN];
__device__ __align__(256) int   g_outdeg[NN];
__device__ __align__(256) int   g_fill[NN];
__device__ __align__(256) int   g_rowptr[NN + 1];
__device__ __align__(256) int   g_blocksums[256];
__device__ __align__(256) int   g_esrc[MAXE];
__device__ __align__(256) float g_snorm[NN];
__device__ __align__(256) float g_dnorm[NN];
__device__ __align__(256) float g_agg[(size_t)NN_PAD * 256];
__device__ __align__(256) float g_h[(size_t)NN_PAD * 256];
__device__ __align__(256) float g_xm[(size_t)NN_PAD * 64];

// ---------------- degrees / norms -------------------------------------------
__global__ void zero_init_kernel() {
    int i = blockIdx.x * blockDim.x + threadIdx.x;
    if (i < NN) { g_indeg[i] = 0; g_outdeg[i] = 0; g_fill[i] = 0; }
}

__global__ void degree_kernel(const int* __restrict__ src,
                              const int* __restrict__ dst, int nE) {
    int i = blockIdx.x * blockDim.x + threadIdx.x;
    if (i < nE) {
        atomicAdd(&g_outdeg[src[i]], 1);
        atomicAdd(&g_indeg[dst[i]], 1);
    }
}

__global__ void norm_kernel() {
    int i = blockIdx.x * blockDim.x + threadIdx.x;
    if (i < NN) {
        g_snorm[i] = rsqrtf(fmaxf((float)g_outdeg[i], 1.f));
        g_dnorm[i] = rsqrtf(fmaxf((float)g_indeg[i], 1.f));
    }
}

// ---------------- CSR build: scan + bucket fill ------------------------------
__global__ void scan1_kernel() {
    __shared__ int sh[SCAN_BS];
    int i = blockIdx.x * SCAN_BS + threadIdx.x;
    int v = (i < NN) ? g_indeg[i] : 0;
    sh[threadIdx.x] = v;
    __syncthreads();
    for (int off = 1; off < SCAN_BS; off <<= 1) {
        int t = (threadIdx.x >= off) ? sh[threadIdx.x - off] : 0;
        __syncthreads();
        sh[threadIdx.x] += t;
        __syncthreads();
    }
    if (i < NN) g_rowptr[i] = sh[threadIdx.x] - v;
    if (threadIdx.x == SCAN_BS - 1) g_blocksums[blockIdx.x] = sh[threadIdx.x];
}

__global__ void scan2_kernel(int nb) {
    __shared__ int sh[256];
    int t = threadIdx.x;
    int v = (t < nb) ? g_blocksums[t] : 0;
    sh[t] = v;
    __syncthreads();
    for (int off = 1; off < 256; off <<= 1) {
        int u = (t >= off) ? sh[t - off] : 0;
        __syncthreads();
        sh[t] += u;
        __syncthreads();
    }
    if (t < nb) g_blocksums[t] = sh[t] - v;
}

__global__ void scan3_kernel(int nE) {
    int i = blockIdx.x * SCAN_BS + threadIdx.x;
    if (i < NN) g_rowptr[i] += g_blocksums[blockIdx.x];
    if (i == 0) g_rowptr[NN] = nE;
}

__global__ void fillcsr_kernel(const int* __restrict__ src,
                               const int* __restrict__ dst, int nE) {
    int i = blockIdx.x * blockDim.x + threadIdx.x;
    if (i < nE) {
        int d = dst[i];
        int pos = g_rowptr[d] + atomicAdd(&g_fill[d], 1);
        g_esrc[pos] = src[i];
    }
}

// ---------------- gather aggregation (no atomics) ----------------------------
__global__ __launch_bounds__(256) void gather256_kernel(
    const float* __restrict__ x, float* __restrict__ out) {
    int v = (blockIdx.x * blockDim.x + threadIdx.x) >> 5;
    int lane = threadIdx.x & 31;
    if (v >= NN) return;
    int row = g_rowptr[v];
    int end = g_rowptr[v + 1];
    float4 acc0 = make_float4(0.f, 0.f, 0.f, 0.f);
    float4 acc1 = make_float4(0.f, 0.f, 0.f, 0.f);
    for (int base = row; base < end; base += 32) {
        int n = min(32, end - base);
        int s = 0;
        float w = 0.f;
        if (lane < n) { s = __ldg(&g_esrc[base + lane]); w = __ldg(&g_snorm[s]); }
        int k = 0;
        for (; k + 2 <= n; k += 2) {
            int s0 = __shfl_sync(0xffffffffu, s, k);
            int s1 = __shfl_sync(0xffffffffu, s, k + 1);
            float w0 = __shfl_sync(0xffffffffu, w, k);
            float w1 = __shfl_sync(0xffffffffu, w, k + 1);
            const float4* r0 = (const float4*)(x + (size_t)s0 * 256);
            const float4* r1 = (const float4*)(x + (size_t)s1 * 256);
            float4 a0 = __ldg(&r0[lane]);
            float4 b0 = __ldg(&r0[lane + 32]);
            float4 a1 = __ldg(&r1[lane]);
            float4 b1 = __ldg(&r1[lane + 32]);
            acc0.x = fmaf(w0, a0.x, fmaf(w1, a1.x, acc0.x));
            acc0.y = fmaf(w0, a0.y, fmaf(w1, a1.y, acc0.y));
            acc0.z = fmaf(w0, a0.z, fmaf(w1, a1.z, acc0.z));
            acc0.w = fmaf(w0, a0.w, fmaf(w1, a1.w, acc0.w));
            acc1.x = fmaf(w0, b0.x, fmaf(w1, b1.x, acc1.x));
            acc1.y = fmaf(w0, b0.y, fmaf(w1, b1.y, acc1.y));
            acc1.z = fmaf(w0, b0.z, fmaf(w1, b1.z, acc1.z));
            acc1.w = fmaf(w0, b0.w, fmaf(w1, b1.w, acc1.w));
        }
        if (k < n) {
            int s0 = __shfl_sync(0xffffffffu, s, k);
            float w0 = __shfl_sync(0xffffffffu, w, k);
            const float4* r0 = (const float4*)(x + (size_t)s0 * 256);
            float4 a0 = __ldg(&r0[lane]);
            float4 b0 = __ldg(&r0[lane + 32]);
            acc0.x = fmaf(w0, a0.x, acc0.x);
            acc0.y = fmaf(w0, a0.y, acc0.y);
            acc0.z = fmaf(w0, a0.z, acc0.z);
            acc0.w = fmaf(w0, a0.w, acc0.w);
            acc1.x = fmaf(w0, b0.x, acc1.x);
            acc1.y = fmaf(w0, b0.y, acc1.y);
            acc1.z = fmaf(w0, b0.z, acc1.z);
            acc1.w = fmaf(w0, b0.w, acc1.w);
        }
    }
    float4* op = (float4*)(out + (size_t)v * 256);
    op[lane] = acc0;
    op[lane + 32] = acc1;
}

__global__ __launch_bounds__(256) void gather64_kernel(
    const float* __restrict__ x, float* __restrict__ out) {
    int v = (blockIdx.x * blockDim.x + threadIdx.x) >> 5;
    int lane = threadIdx.x & 31;
    if (v >= NN) return;
    int row = g_rowptr[v];
    int end = g_rowptr[v + 1];
    float2 acc = make_float2(0.f, 0.f);
    for (int base = row; base < end; base += 32) {
        int n = min(32, end - base);
        int s = 0;
        if (lane < n) s = __ldg(&g_esrc[base + lane]);
        int k = 0;
        for (; k + 4 <= n; k += 4) {
            int s0 = __shfl_sync(0xffffffffu, s, k);
            int s1 = __shfl_sync(0xffffffffu, s, k + 1);
            int s2 = __shfl_sync(0xffffffffu, s, k + 2);
            int s3 = __shfl_sync(0xffffffffu, s, k + 3);
            float2 a0 = __ldg((const float2*)(x + (size_t)s0 * 64) + lane);
            float2 a1 = __ldg((const float2*)(x + (size_t)s1 * 64) + lane);
            float2 a2 = __ldg((const float2*)(x + (size_t)s2 * 64) + lane);
            float2 a3 = __ldg((const float2*)(x + (size_t)s3 * 64) + lane);
            acc.x += (a0.x + a1.x) + (a2.x + a3.x);
            acc.y += (a0.y + a1.y) + (a2.y + a3.y);
        }
        for (; k < n; k++) {
            int s0 = __shfl_sync(0xffffffffu, s, k);
            float2 a0 = __ldg((const float2*)(x + (size_t)s0 * 64) + lane);
            acc.x += a0.x;
            acc.y += a0.y;
        }
    }
    float w = g_dnorm[v];
    ((float2*)(out + (size_t)v * 64))[lane] = make_float2(acc.x * w, acc.y * w);
}

// ---------------- wide TF32 GEMM: BM=128, BN=128, warp tile 64x32 ------------
// C = act( (A * norm[:,None]) @ W ), K=256, N=256 with gridDim.y=2 (A read 2x).
template <bool RELU>
__global__ __launch_bounds__(256, 2) void gemm128_tf32_kernel(
    const float* __restrict__ A, const float* __restrict__ W,
    const float* __restrict__ norm, float* __restrict__ C, int M, int N) {
    constexpr int BM = 128, BN = 128, BK = 32;
    constexpr int APAD = 8, BPAD = 8;
    __shared__ float As[BM][BK + APAD];   // 20.5 KB
    __shared__ float Bs[BK][BN + BPAD];   // 17.4 KB

    const int t = threadIdx.x;
    const int warp = t >> 5;
    const int wm = warp >> 2;   // 0..1 -> 64-row strip
    const int wn = warp & 3;    // 0..3 -> 32-col strip
    const int row0 = blockIdx.x * BM;
    const int col0 = blockIdx.y * BN;

    // A tile: 128 rows x 32 cols; thread t -> row t>>1, cols (t&1)*16 + q*4
    const int a_row = t >> 1;
    const int a_c0 = (t & 1) * 16;
    const bool a_ok = (row0 + a_row) < M;
    const float nrm = a_ok ? __ldg(&norm[row0 + a_row]) : 0.f;
    const float* Aptr = A + (size_t)(row0 + a_row) * 256 + a_c0;

    // B tile: 32 rows x 128 cols = 1024 float4; thread t -> row t>>3,
    // 4 float4 at cols (t&7)*16 + q*4
    const int b_row = t >> 3;
    const int b_c0 = (t & 7) * 16;

    wmma::fragment<wmma::accumulator, 16, 16, 8, float> acc[4][2];
#pragma unroll
    for (int i = 0; i < 4; i++)
#pragma unroll
        for (int j = 0; j < 2; j++) wmma::fill_fragment(acc[i][j], 0.f);

    float4 ar[4], br[4];
#pragma unroll
    for (int q = 0; q < 4; q++) ar[q] = *(const float4*)(Aptr + q * 4);
#pragma unroll
    for (int q = 0; q < 4; q++)
        br[q] = *(const float4*)&W[(size_t)b_row * N + col0 + b_c0 + q * 4];

    auto store_tiles = [&]() {
#pragma unroll
        for (int q = 0; q < 4; q++) {
            As[a_row][a_c0 + q * 4 + 0] = wmma::__float_to_tf32(ar[q].x * nrm);
            As[a_row][a_c0 + q * 4 + 1] = wmma::__float_to_tf32(ar[q].y * nrm);
            As[a_row][a_c0 + q * 4 + 2] = wmma::__float_to_tf32(ar[q].z * nrm);
            As[a_row][a_c0 + q * 4 + 3] = wmma::__float_to_tf32(ar[q].w * nrm);
        }
#pragma unroll
        for (int q = 0; q < 4; q++) {
            Bs[b_row][b_c0 + q * 4 + 0] = wmma::__float_to_tf32(br[q].x);
            Bs[b_row][b_c0 + q * 4 + 1] = wmma::__float_to_tf32(br[q].y);
            Bs[b_row][b_c0 + q * 4 + 2] = wmma::__float_to_tf32(br[q].z);
            Bs[b_row][b_c0 + q * 4 + 3] = wmma::__float_to_tf32(br[q].w);
        }
    };

    store_tiles();
    __syncthreads();

    for (int k0 = 0; k0 < 256; k0 += BK) {
        const bool has_next = (k0 + BK) < 256;
        if (has_next) {
#pragma unroll
            for (int q = 0; q < 4; q++)
                ar[q] = *(const float4*)(Aptr + k0 + BK + q * 4);
#pragma unroll
            for (int q = 0; q < 4; q++)
                br[q] = *(const float4*)&W[(size_t)(k0 + BK + b_row) * N + col0 + b_c0 + q * 4];
        }
#pragma unroll
        for (int kk = 0; kk < BK; kk += 8) {
            wmma::fragment<wmma::matrix_a, 16, 16, 8, wmma::precision::tf32,
                           wmma::row_major> af[4];
            wmma::fragment<wmma::matrix_b, 16, 16, 8, wmma::precision::tf32,
                           wmma::row_major> bf[2];
#pragma unroll
            for (int i = 0; i < 4; i++)
                wmma::load_matrix_sync(af[i], &As[wm * 64 + i * 16][kk], BK + APAD);
#pragma unroll
            for (int j = 0; j < 2; j++)
                wmma::load_matrix_sync(bf[j], &Bs[kk][wn * 32 + j * 16], BN + BPAD);
#pragma unroll
            for (int i = 0; i < 4; i++)
#pragma unroll
                for (int j = 0; j < 2; j++)
                    wmma::mma_sync(acc[i][j], af[i], bf[j], acc[i][j]);
        }
        __syncthreads();
        if (has_next) {
            store_tiles();
            __syncthreads();
        }
    }

#pragma unroll
    for (int i = 0; i < 4; i++)
#pragma unroll
        for (int j = 0; j < 2; j++) {
            if (RELU) {
#pragma unroll
                for (int e = 0; e < acc[i][j].num_elements; e++)
                    acc[i][j].x[e] = fmaxf(acc[i][j].x[e], 0.f);
            }
            float* cptr = C + (size_t)(row0 + wm * 64 + i * 16) * N +
                          col0 + wn * 32 + j * 16;
            wmma::store_matrix_sync(cptr, acc[i][j], N, wmma::mem_row_major);
        }
}

// ---------------- layer-2 GEMM (N=64): xm = (h * snorm) @ W2 -----------------
template <bool RELU>
__global__ __launch_bounds__(256, 2) void gemm64_tf32_kernel(
    const float* __restrict__ A, const float* __restrict__ W,
    const float* __restrict__ norm, float* __restrict__ C, int M, int N) {
    constexpr int BM = 128, BN = 64, BK = 32;
    constexpr int APAD = 8, BPAD = 8;
    __shared__ float As[BM][BK + APAD];
    __shared__ float Bs[BK][BN + BPAD];

    const int t = threadIdx.x;
    const int warp = t >> 5;
    const int wm = warp >> 1;
    const int wn = warp & 1;
    const int row0 = blockIdx.x * BM;
    const int col0 = 0;

    const int a_row = t >> 1;
    const int a_c0 = (t & 1) * 16;
    const bool a_ok = (row0 + a_row) < M;
    const float nrm = a_ok ? __ldg(&norm[row0 + a_row]) : 0.f;
    const float* Aptr = A + (size_t)(row0 + a_row) * 256 + a_c0;

    const int b_row = t >> 3;
    const int b_c0 = (t & 7) * 8;

    wmma::fragment<wmma::accumulator, 16, 16, 8, float> acc[2][2];
#pragma unroll
    for (int i = 0; i < 2; i++)
#pragma unroll
        for (int j = 0; j < 2; j++) wmma::fill_fragment(acc[i][j], 0.f);

    float4 ar[4], br[2];
#pragma unroll
    for (int q = 0; q < 4; q++) ar[q] = *(const float4*)(Aptr + q * 4);
#pragma unroll
    for (int q = 0; q < 2; q++)
        br[q] = *(const float4*)&W[(size_t)b_row * N + col0 + b_c0 + q * 4];

    auto store_tiles = [&]() {
#pragma unroll
        for (int q = 0; q < 4; q++) {
            As[a_row][a_c0 + q * 4 + 0] = wmma::__float_to_tf32(ar[q].x * nrm);
            As[a_row][a_c0 + q * 4 + 1] = wmma::__float_to_tf32(ar[q].y * nrm);
            As[a_row][a_c0 + q * 4 + 2] = wmma::__float_to_tf32(ar[q].z * nrm);
            As[a_row][a_c0 + q * 4 + 3] = wmma::__float_to_tf32(ar[q].w * nrm);
        }
#pragma unroll
        for (int q = 0; q < 2; q++) {
            Bs[b_row][b_c0 + q * 4 + 0] = wmma::__float_to_tf32(br[q].x);
            Bs[b_row][b_c0 + q * 4 + 1] = wmma::__float_to_tf32(br[q].y);
            Bs[b_row][b_c0 + q * 4 + 2] = wmma::__float_to_tf32(br[q].z);
            Bs[b_row][b_c0 + q * 4 + 3] = wmma::__float_to_tf32(br[q].w);
        }
    };

    store_tiles();
    __syncthreads();

    for (int k0 = 0; k0 < 256; k0 += BK) {
        const bool has_next = (k0 + BK) < 256;
        if (has_next) {
#pragma unroll
            for (int q = 0; q < 4; q++)
                ar[q] = *(const float4*)(Aptr + k0 + BK + q * 4);
#pragma unroll
            for (int q = 0; q < 2; q++)
                br[q] = *(const float4*)&W[(size_t)(k0 + BK + b_row) * N + col0 + b_c0 + q * 4];
        }
#pragma unroll
        for (int kk = 0; kk < BK; kk += 8) {
            wmma::fragment<wmma::matrix_a, 16, 16, 8, wmma::precision::tf32,
                           wmma::row_major> af[2];
            wmma::fragment<wmma::matrix_b, 16, 16, 8, wmma::precision::tf32,
                           wmma::row_major> bf[2];
#pragma unroll
            for (int i = 0; i < 2; i++)
                wmma::load_matrix_sync(af[i], &As[wm * 32 + i * 16][kk], BK + APAD);
#pragma unroll
            for (int j = 0; j < 2; j++)
                wmma::load_matrix_sync(bf[j], &Bs[kk][wn * 32 + j * 16], BN + BPAD);
#pragma unroll
            for (int i = 0; i < 2; i++)
#pragma unroll
                for (int j = 0; j < 2; j++)
                    wmma::mma_sync(acc[i][j], af[i], bf[j], acc[i][j]);
        }
        __syncthreads();
        if (has_next) {
            store_tiles();
            __syncthreads();
        }
    }

#pragma unroll
    for (int i = 0; i < 2; i++)
#pragma unroll
        for (int j = 0; j < 2; j++) {
            if (RELU) {
#pragma unroll
                for (int e = 0; e < acc[i][j].num_elements; e++)
                    acc[i][j].x[e] = fmaxf(acc[i][j].x[e], 0.f);
            }
            float* cptr = C + (size_t)(row0 + wm * 32 + i * 16) * N +
                          col0 + wn * 32 + j * 16;
            wmma::store_matrix_sync(cptr, acc[i][j], N, wmma::mem_row_major);
        }
}

// ---------------- launch -----------------------------------------------------
extern "C" void kernel_launch(void* const* d_in, const int* in_sizes, int n_in,
                              void* d_out, int out_size) {
    const float* feat = (const float*)d_in[0];
    const int* src = (const int*)d_in[1];
    const int* dst = (const int*)d_in[2];
    const float* W0 = (const float*)d_in[3];
    const float* W1 = (const float*)d_in[4];
    const float* W2 = (const float*)d_in[5];
    float* out = (float*)d_out;
    const int nE = in_sizes[1];

    float *agg, *h, *xm, *snorm, *dnorm;
    cudaGetSymbolAddress((void**)&agg, g_agg);
    cudaGetSymbolAddress((void**)&h, g_h);
    cudaGetSymbolAddress((void**)&xm, g_xm);
    cudaGetSymbolAddress((void**)&snorm, g_snorm);
    cudaGetSymbolAddress((void**)&dnorm, g_dnorm);

    const int T = 256;
    const int NB = (NN + SCAN_BS - 1) / SCAN_BS;      // 196
    const int gemm_rows = NN_PAD / 128;               // 782
    const int gather_blocks = (NN * 32 + T - 1) / T;  // 12500

    // degrees + norms + CSR build
    zero_init_kernel<<<(NN + T - 1) / T, T>>>();
    degree_kernel<<<(nE + T - 1) / T, T>>>(src, dst, nE);
    norm_kernel<<<(NN + T - 1) / T, T>>>();
    scan1_kernel<<<NB, SCAN_BS>>>();
    scan2_kernel<<<1, 256>>>(NB);
    scan3_kernel<<<NB, SCAN_BS>>>(nE);
    fillcsr_kernel<<<(nE + T - 1) / T, T>>>(src, dst, nE);

    // layer 0: agg = A^T (feat * snorm); h = relu((agg * dnorm) @ W0)
    gather256_kernel<<<gather_blocks, T>>>(feat, agg);
    gemm128_tf32_kernel<true><<<dim3(gemm_rows, 2), T>>>(agg, W0, dnorm, h, NN, 256);

    // layer 1
    gather256_kernel<<<gather_blocks, T>>>(h, agg);
    gemm128_tf32_kernel<true><<<dim3(gemm_rows, 2), T>>>(agg, W1, dnorm, h, NN, 256);

    // layer 2: xm = (h * snorm) @ W2; out = dnorm * (A^T xm)
    gemm64_tf32_kernel<false><<<dim3(gemm_rows, 1), T>>>(h, W2, snorm, xm, NN, 64);
    gather64_kernel<<<gather_blocks, T>>>(xm, out);
}

// round 7
// speedup vs baseline: 2.1213x; 1.1192x over previous
#include <cuda_runtime.h>
#include <cuda_fp16.h>
#include <mma.h>
#include <cstdint>

using namespace nvcuda;

#define NN 100000
#define NN_PAD 100096   // 782 * 128
#define MAXE 3300000
#define SCAN_BS 512

// ---------------- scratch (static device globals) ---------------------------
__device__ __align__(256) int    g_indeg[NN];
__device__ __align__(256) int    g_outdeg[NN];
__device__ __align__(256) int    g_fill[NN];
__device__ __align__(256) int    g_rowptr[NN + 1];
__device__ __align__(256) int    g_blocksums[256];
__device__ __align__(256) int    g_esrc[MAXE];
__device__ __align__(256) float  g_snorm[NN];
__device__ __align__(256) float  g_dnorm[NN];
__device__ __align__(256) float  g_agg[(size_t)NN_PAD * 256];   // fp32 GEMM input
__device__ __align__(256) float  g_h[(size_t)NN_PAD * 256];     // fp32 GEMM output
__device__ __align__(256) __half g_xh[(size_t)NN_PAD * 256];    // fp16 gather input
__device__ __align__(256) float  g_xm[(size_t)NN_PAD * 64];

// ---------------- degrees / norms -------------------------------------------
__global__ void zero_init_kernel() {
    int i = blockIdx.x * blockDim.x + threadIdx.x;
    if (i < NN) { g_indeg[i] = 0; g_outdeg[i] = 0; g_fill[i] = 0; }
}

__global__ void degree_kernel(const int* __restrict__ src,
                              const int* __restrict__ dst, int nE) {
    int i = blockIdx.x * blockDim.x + threadIdx.x;
    if (i < nE) {
        atomicAdd(&g_outdeg[src[i]], 1);
        atomicAdd(&g_indeg[dst[i]], 1);
    }
}

__global__ void norm_kernel() {
    int i = blockIdx.x * blockDim.x + threadIdx.x;
    if (i < NN) {
        g_snorm[i] = rsqrtf(fmaxf((float)g_outdeg[i], 1.f));
        g_dnorm[i] = rsqrtf(fmaxf((float)g_indeg[i], 1.f));
    }
}

// ---------------- CSR build: scan + bucket fill ------------------------------
__global__ void scan1_kernel() {
    __shared__ int sh[SCAN_BS];
    int i = blockIdx.x * SCAN_BS + threadIdx.x;
    int v = (i < NN) ? g_indeg[i] : 0;
    sh[threadIdx.x] = v;
    __syncthreads();
    for (int off = 1; off < SCAN_BS; off <<= 1) {
        int t = (threadIdx.x >= off) ? sh[threadIdx.x - off] : 0;
        __syncthreads();
        sh[threadIdx.x] += t;
        __syncthreads();
    }
    if (i < NN) g_rowptr[i] = sh[threadIdx.x] - v;
    if (threadIdx.x == SCAN_BS - 1) g_blocksums[blockIdx.x] = sh[threadIdx.x];
}

__global__ void scan2_kernel(int nb) {
    __shared__ int sh[256];
    int t = threadIdx.x;
    int v = (t < nb) ? g_blocksums[t] : 0;
    sh[t] = v;
    __syncthreads();
    for (int off = 1; off < 256; off <<= 1) {
        int u = (t >= off) ? sh[t - off] : 0;
        __syncthreads();
        sh[t] += u;
        __syncthreads();
    }
    if (t < nb) g_blocksums[t] = sh[t] - v;
}

__global__ void scan3_kernel(int nE) {
    int i = blockIdx.x * SCAN_BS + threadIdx.x;
    if (i < NN) g_rowptr[i] += g_blocksums[blockIdx.x];
    if (i == 0) g_rowptr[NN] = nE;
}

__global__ void fillcsr_kernel(const int* __restrict__ src,
                               const int* __restrict__ dst, int nE) {
    int i = blockIdx.x * blockDim.x + threadIdx.x;
    if (i < nE) {
        int d = dst[i];
        int pos = g_rowptr[d] + atomicAdd(&g_fill[d], 1);
        g_esrc[pos] = src[i];
    }
}

// ---------------- fp32 -> fp16 convert (streaming) ---------------------------
// each thread converts 8 floats -> 8 halves (one uint4 store)
__global__ void convert_half_kernel(const float* __restrict__ in,
                                    __half* __restrict__ out, int n8) {
    int i = blockIdx.x * blockDim.x + threadIdx.x;
    if (i >= n8) return;
    float4 a = ((const float4*)in)[i * 2];
    float4 b = ((const float4*)in)[i * 2 + 1];
    __half2 h[4];
    h[0] = __floats2half2_rn(a.x, a.y);
    h[1] = __floats2half2_rn(a.z, a.w);
    h[2] = __floats2half2_rn(b.x, b.y);
    h[3] = __floats2half2_rn(b.z, b.w);
    ((uint4*)out)[i] = *(const uint4*)h;
}

// ---------------- gather256 from fp16 input, fp32 accumulate -----------------
// one warp per dst node; lane covers 8 consecutive feats (one 16B load/edge)
__global__ __launch_bounds__(256) void gather256h_kernel(
    const __half* __restrict__ x, float* __restrict__ out) {
    int v = (blockIdx.x * blockDim.x + threadIdx.x) >> 5;
    int lane = threadIdx.x & 31;
    if (v >= NN) return;
    int row = g_rowptr[v];
    int end = g_rowptr[v + 1];
    float acc[8] = {0.f, 0.f, 0.f, 0.f, 0.f, 0.f, 0.f, 0.f};

    for (int base = row; base < end; base += 32) {
        int n = min(32, end - base);
        int s = 0;
        float w = 0.f;
        if (lane < n) { s = __ldg(&g_esrc[base + lane]); w = __ldg(&g_snorm[s]); }
        int k = 0;
        for (; k + 4 <= n; k += 4) {
            int s0 = __shfl_sync(0xffffffffu, s, k);
            int s1 = __shfl_sync(0xffffffffu, s, k + 1);
            int s2 = __shfl_sync(0xffffffffu, s, k + 2);
            int s3 = __shfl_sync(0xffffffffu, s, k + 3);
            float w0 = __shfl_sync(0xffffffffu, w, k);
            float w1 = __shfl_sync(0xffffffffu, w, k + 1);
            float w2 = __shfl_sync(0xffffffffu, w, k + 2);
            float w3 = __shfl_sync(0xffffffffu, w, k + 3);
            uint4 u0 = __ldg((const uint4*)(x + (size_t)s0 * 256) + lane);
            uint4 u1 = __ldg((const uint4*)(x + (size_t)s1 * 256) + lane);
            uint4 u2 = __ldg((const uint4*)(x + (size_t)s2 * 256) + lane);
            uint4 u3 = __ldg((const uint4*)(x + (size_t)s3 * 256) + lane);
            const __half2* p0 = (const __half2*)&u0;
            const __half2* p1 = (const __half2*)&u1;
            const __half2* p2 = (const __half2*)&u2;
            const __half2* p3 = (const __half2*)&u3;
#pragma unroll
            for (int j = 0; j < 4; j++) {
                float2 f0 = __half22float2(p0[j]);
                float2 f1 = __half22float2(p1[j]);
                float2 f2 = __half22float2(p2[j]);
                float2 f3 = __half22float2(p3[j]);
                acc[j * 2 + 0] += (w0 * f0.x + w1 * f1.x) + (w2 * f2.x + w3 * f3.x);
                acc[j * 2 + 1] += (w0 * f0.y + w1 * f1.y) + (w2 * f2.y + w3 * f3.y);
            }
        }
        for (; k < n; k++) {
            int s0 = __shfl_sync(0xffffffffu, s, k);
            float w0 = __shfl_sync(0xffffffffu, w, k);
            uint4 u0 = __ldg((const uint4*)(x + (size_t)s0 * 256) + lane);
            const __half2* p0 = (const __half2*)&u0;
#pragma unroll
            for (int j = 0; j < 4; j++) {
                float2 f0 = __half22float2(p0[j]);
                acc[j * 2 + 0] += w0 * f0.x;
                acc[j * 2 + 1] += w0 * f0.y;
            }
        }
    }
    float* op = out + (size_t)v * 256 + lane * 8;
    *(float4*)(op + 0) = make_float4(acc[0], acc[1], acc[2], acc[3]);
    *(float4*)(op + 4) = make_float4(acc[4], acc[5], acc[6], acc[7]);
}

// ---------------- gather64 (fp32): out[v] = dnorm[v] * sum_e xm[src_e] -------
__global__ __launch_bounds__(256) void gather64_kernel(
    const float* __restrict__ x, float* __restrict__ out) {
    int v = (blockIdx.x * blockDim.x + threadIdx.x) >> 5;
    int lane = threadIdx.x & 31;
    if (v >= NN) return;
    int row = g_rowptr[v];
    int end = g_rowptr[v + 1];
    float2 acc = make_float2(0.f, 0.f);
    for (int base = row; base < end; base += 32) {
        int n = min(32, end - base);
        int s = 0;
        if (lane < n) s = __ldg(&g_esrc[base + lane]);
        int k = 0;
        for (; k + 4 <= n; k += 4) {
            int s0 = __shfl_sync(0xffffffffu, s, k);
            int s1 = __shfl_sync(0xffffffffu, s, k + 1);
            int s2 = __shfl_sync(0xffffffffu, s, k + 2);
            int s3 = __shfl_sync(0xffffffffu, s, k + 3);
            float2 a0 = __ldg((const float2*)(x + (size_t)s0 * 64) + lane);
            float2 a1 = __ldg((const float2*)(x + (size_t)s1 * 64) + lane);
            float2 a2 = __ldg((const float2*)(x + (size_t)s2 * 64) + lane);
            float2 a3 = __ldg((const float2*)(x + (size_t)s3 * 64) + lane);
            acc.x += (a0.x + a1.x) + (a2.x + a3.x);
            acc.y += (a0.y + a1.y) + (a2.y + a3.y);
        }
        for (; k < n; k++) {
            int s0 = __shfl_sync(0xffffffffu, s, k);
            float2 a0 = __ldg((const float2*)(x + (size_t)s0 * 64) + lane);
            acc.x += a0.x;
            acc.y += a0.y;
        }
    }
    float w = g_dnorm[v];
    ((float2*)(out + (size_t)v * 64))[lane] = make_float2(acc.x * w, acc.y * w);
}

// ---------------- wide TF32 GEMM: BM=128, BN=128, warp tile 64x32 ------------
template <bool RELU>
__global__ __launch_bounds__(256, 2) void gemm128_tf32_kernel(
    const float* __restrict__ A, const float* __restrict__ W,
    const float* __restrict__ norm, float* __restrict__ C, int M, int N) {
    constexpr int BM = 128, BN = 128, BK = 32;
    constexpr int APAD = 8, BPAD = 8;
    __shared__ float As[BM][BK + APAD];
    __shared__ float Bs[BK][BN + BPAD];

    const int t = threadIdx.x;
    const int warp = t >> 5;
    const int wm = warp >> 2;
    const int wn = warp & 3;
    const int row0 = blockIdx.x * BM;
    const int col0 = blockIdx.y * BN;

    const int a_row = t >> 1;
    const int a_c0 = (t & 1) * 16;
    const bool a_ok = (row0 + a_row) < M;
    const float nrm = a_ok ? __ldg(&norm[row0 + a_row]) : 0.f;
    const float* Aptr = A + (size_t)(row0 + a_row) * 256 + a_c0;

    const int b_row = t >> 3;
    const int b_c0 = (t & 7) * 16;

    wmma::fragment<wmma::accumulator, 16, 16, 8, float> acc[4][2];
#pragma unroll
    for (int i = 0; i < 4; i++)
#pragma unroll
        for (int j = 0; j < 2; j++) wmma::fill_fragment(acc[i][j], 0.f);

    float4 ar[4], br[4];
#pragma unroll
    for (int q = 0; q < 4; q++) ar[q] = *(const float4*)(Aptr + q * 4);
#pragma unroll
    for (int q = 0; q < 4; q++)
        br[q] = *(const float4*)&W[(size_t)b_row * N + col0 + b_c0 + q * 4];

    auto store_tiles = [&]() {
#pragma unroll
        for (int q = 0; q < 4; q++) {
            As[a_row][a_c0 + q * 4 + 0] = wmma::__float_to_tf32(ar[q].x * nrm);
            As[a_row][a_c0 + q * 4 + 1] = wmma::__float_to_tf32(ar[q].y * nrm);
            As[a_row][a_c0 + q * 4 + 2] = wmma::__float_to_tf32(ar[q].z * nrm);
            As[a_row][a_c0 + q * 4 + 3] = wmma::__float_to_tf32(ar[q].w * nrm);
        }
#pragma unroll
        for (int q = 0; q < 4; q++) {
            Bs[b_row][b_c0 + q * 4 + 0] = wmma::__float_to_tf32(br[q].x);
            Bs[b_row][b_c0 + q * 4 + 1] = wmma::__float_to_tf32(br[q].y);
            Bs[b_row][b_c0 + q * 4 + 2] = wmma::__float_to_tf32(br[q].z);
            Bs[b_row][b_c0 + q * 4 + 3] = wmma::__float_to_tf32(br[q].w);
        }
    };

    store_tiles();
    __syncthreads();

    for (int k0 = 0; k0 < 256; k0 += BK) {
        const bool has_next = (k0 + BK) < 256;
        if (has_next) {
#pragma unroll
            for (int q = 0; q < 4; q++)
                ar[q] = *(const float4*)(Aptr + k0 + BK + q * 4);
#pragma unroll
            for (int q = 0; q < 4; q++)
                br[q] = *(const float4*)&W[(size_t)(k0 + BK + b_row) * N + col0 + b_c0 + q * 4];
        }
#pragma unroll
        for (int kk = 0; kk < BK; kk += 8) {
            wmma::fragment<wmma::matrix_a, 16, 16, 8, wmma::precision::tf32,
                           wmma::row_major> af[4];
            wmma::fragment<wmma::matrix_b, 16, 16, 8, wmma::precision::tf32,
                           wmma::row_major> bf[2];
#pragma unroll
            for (int i = 0; i < 4; i++)
                wmma::load_matrix_sync(af[i], &As[wm * 64 + i * 16][kk], BK + APAD);
#pragma unroll
            for (int j = 0; j < 2; j++)
                wmma::load_matrix_sync(bf[j], &Bs[kk][wn * 32 + j * 16], BN + BPAD);
#pragma unroll
            for (int i = 0; i < 4; i++)
#pragma unroll
                for (int j = 0; j < 2; j++)
                    wmma::mma_sync(acc[i][j], af[i], bf[j], acc[i][j]);
        }
        __syncthreads();
        if (has_next) {
            store_tiles();
            __syncthreads();
        }
    }

#pragma unroll
    for (int i = 0; i < 4; i++)
#pragma unroll
        for (int j = 0; j < 2; j++) {
            if (RELU) {
#pragma unroll
                for (int e = 0; e < acc[i][j].num_elements; e++)
                    acc[i][j].x[e] = fmaxf(acc[i][j].x[e], 0.f);
            }
            float* cptr = C + (size_t)(row0 + wm * 64 + i * 16) * N +
                          col0 + wn * 32 + j * 16;
            wmma::store_matrix_sync(cptr, acc[i][j], N, wmma::mem_row_major);
        }
}

// ---------------- layer-2 GEMM (N=64): xm = (h * snorm) @ W2 -----------------
template <bool RELU>
__global__ __launch_bounds__(256, 2) void gemm64_tf32_kernel(
    const float* __restrict__ A, const float* __restrict__ W,
    const float* __restrict__ norm, float* __restrict__ C, int M, int N) {
    constexpr int BM = 128, BN = 64, BK = 32;
    constexpr int APAD = 8, BPAD = 8;
    __shared__ float As[BM][BK + APAD];
    __shared__ float Bs[BK][BN + BPAD];

    const int t = threadIdx.x;
    const int warp = t >> 5;
    const int wm = warp >> 1;
    const int wn = warp & 1;
    const int row0 = blockIdx.x * BM;

    const int a_row = t >> 1;
    const int a_c0 = (t & 1) * 16;
    const bool a_ok = (row0 + a_row) < M;
    const float nrm = a_ok ? __ldg(&norm[row0 + a_row]) : 0.f;
    const float* Aptr = A + (size_t)(row0 + a_row) * 256 + a_c0;

    const int b_row = t >> 3;
    const int b_c0 = (t & 7) * 8;

    wmma::fragment<wmma::accumulator, 16, 16, 8, float> acc[2][2];
#pragma unroll
    for (int i = 0; i < 2; i++)
#pragma unroll
        for (int j = 0; j < 2; j++) wmma::fill_fragment(acc[i][j], 0.f);

    float4 ar[4], br[2];
#pragma unroll
    for (int q = 0; q < 4; q++) ar[q] = *(const float4*)(Aptr + q * 4);
#pragma unroll
    for (int q = 0; q < 2; q++)
        br[q] = *(const float4*)&W[(size_t)b_row * N + b_c0 + q * 4];

    auto store_tiles = [&]() {
#pragma unroll
        for (int q = 0; q < 4; q++) {
            As[a_row][a_c0 + q * 4 + 0] = wmma::__float_to_tf32(ar[q].x * nrm);
            As[a_row][a_c0 + q * 4 + 1] = wmma::__float_to_tf32(ar[q].y * nrm);
            As[a_row][a_c0 + q * 4 + 2] = wmma::__float_to_tf32(ar[q].z * nrm);
            As[a_row][a_c0 + q * 4 + 3] = wmma::__float_to_tf32(ar[q].w * nrm);
        }
#pragma unroll
        for (int q = 0; q < 2; q++) {
            Bs[b_row][b_c0 + q * 4 + 0] = wmma::__float_to_tf32(br[q].x);
            Bs[b_row][b_c0 + q * 4 + 1] = wmma::__float_to_tf32(br[q].y);
            Bs[b_row][b_c0 + q * 4 + 2] = wmma::__float_to_tf32(br[q].z);
            Bs[b_row][b_c0 + q * 4 + 3] = wmma::__float_to_tf32(br[q].w);
        }
    };

    store_tiles();
    __syncthreads();

    for (int k0 = 0; k0 < 256; k0 += BK) {
        const bool has_next = (k0 + BK) < 256;
        if (has_next) {
#pragma unroll
            for (int q = 0; q < 4; q++)
                ar[q] = *(const float4*)(Aptr + k0 + BK + q * 4);
#pragma unroll
            for (int q = 0; q < 2; q++)
                br[q] = *(const float4*)&W[(size_t)(k0 + BK + b_row) * N + b_c0 + q * 4];
        }
#pragma unroll
        for (int kk = 0; kk < BK; kk += 8) {
            wmma::fragment<wmma::matrix_a, 16, 16, 8, wmma::precision::tf32,
                           wmma::row_major> af[2];
            wmma::fragment<wmma::matrix_b, 16, 16, 8, wmma::precision::tf32,
                           wmma::row_major> bf[2];
#pragma unroll
            for (int i = 0; i < 2; i++)
                wmma::load_matrix_sync(af[i], &As[wm * 32 + i * 16][kk], BK + APAD);
#pragma unroll
            for (int j = 0; j < 2; j++)
                wmma::load_matrix_sync(bf[j], &Bs[kk][wn * 32 + j * 16], BN + BPAD);
#pragma unroll
            for (int i = 0; i < 2; i++)
#pragma unroll
                for (int j = 0; j < 2; j++)
                    wmma::mma_sync(acc[i][j], af[i], bf[j], acc[i][j]);
        }
        __syncthreads();
        if (has_next) {
            store_tiles();
            __syncthreads();
        }
    }

#pragma unroll
    for (int i = 0; i < 2; i++)
#pragma unroll
        for (int j = 0; j < 2; j++) {
            if (RELU) {
#pragma unroll
                for (int e = 0; e < acc[i][j].num_elements; e++)
                    acc[i][j].x[e] = fmaxf(acc[i][j].x[e], 0.f);
            }
            float* cptr = C + (size_t)(row0 + wm * 32 + i * 16) * N +
                          wn * 32 + j * 16;
            wmma::store_matrix_sync(cptr, acc[i][j], N, wmma::mem_row_major);
        }
}

// ---------------- launch -----------------------------------------------------
extern "C" void kernel_launch(void* const* d_in, const int* in_sizes, int n_in,
                              void* d_out, int out_size) {
    const float* feat = (const float*)d_in[0];
    const int* src = (const int*)d_in[1];
    const int* dst = (const int*)d_in[2];
    const float* W0 = (const float*)d_in[3];
    const float* W1 = (const float*)d_in[4];
    const float* W2 = (const float*)d_in[5];
    float* out = (float*)d_out;
    const int nE = in_sizes[1];

    float *agg, *h, *xm, *snorm, *dnorm;
    __half* xh;
    cudaGetSymbolAddress((void**)&agg, g_agg);
    cudaGetSymbolAddress((void**)&h, g_h);
    cudaGetSymbolAddress((void**)&xh, g_xh);
    cudaGetSymbolAddress((void**)&xm, g_xm);
    cudaGetSymbolAddress((void**)&snorm, g_snorm);
    cudaGetSymbolAddress((void**)&dnorm, g_dnorm);

    const int T = 256;
    const int NB = (NN + SCAN_BS - 1) / SCAN_BS;      // 196
    const int gemm_rows = NN_PAD / 128;               // 782
    const int gather_blocks = (NN * 32 + T - 1) / T;  // 12500
    const int conv8 = NN * 256 / 8;                   // 3.2M

    // degrees + norms + CSR build
    zero_init_kernel<<<(NN + T - 1) / T, T>>>();
    degree_kernel<<<(nE + T - 1) / T, T>>>(src, dst, nE);
    norm_kernel<<<(NN + T - 1) / T, T>>>();
    scan1_kernel<<<NB, SCAN_BS>>>();
    scan2_kernel<<<1, 256>>>(NB);
    scan3_kernel<<<NB, SCAN_BS>>>(nE);
    fillcsr_kernel<<<(nE + T - 1) / T, T>>>(src, dst, nE);

    // layer 0
    convert_half_kernel<<<(conv8 + T - 1) / T, T>>>(feat, xh, conv8);
    gather256h_kernel<<<gather_blocks, T>>>(xh, agg);
    gemm128_tf32_kernel<true><<<dim3(gemm_rows, 2), T>>>(agg, W0, dnorm, h, NN, 256);

    // layer 1
    convert_half_kernel<<<(conv8 + T - 1) / T, T>>>(h, xh, conv8);
    gather256h_kernel<<<gather_blocks, T>>>(xh, agg);
    gemm128_tf32_kernel<true><<<dim3(gemm_rows, 2), T>>>(agg, W1, dnorm, h, NN, 256);

    // layer 2
    gemm64_tf32_kernel<false><<<dim3(gemm_rows, 1), T>>>(h, W2, snorm, xm, NN, 64);
    gather64_kernel<<<gather_blocks, T>>>(xm, out);
}

// round 8
// speedup vs baseline: 3.7616x; 1.7733x over previous
#include <cuda_runtime.h>
#include <cuda_fp16.h>
#include <mma.h>
#include <cstdint>

using namespace nvcuda;

#define NN 100000
#define NN_PAD 100096   // 782 * 128
#define MAXE 3300000
#define SCAN_BS 512

// ---------------- scratch (static device globals; zero-initialized) ---------
__device__ __align__(256) int    g_indeg[NN];
__device__ __align__(256) int    g_outdeg[NN];
__device__ __align__(256) int    g_fill[NN];
__device__ __align__(256) int    g_rowptr[NN + 1];
__device__ __align__(256) int    g_blocksums[256];
__device__ __align__(256) int    g_esrc[MAXE];
__device__ __align__(256) float  g_snorm[NN];
__device__ __align__(256) float  g_dnorm[NN];
__device__ __align__(256) __half g_xh[(size_t)NN_PAD * 256];    // feat fp16
__device__ __align__(256) __half g_aggh[(size_t)NN_PAD * 256];  // agg fp16
__device__ __align__(256) __half g_hh[(size_t)NN_PAD * 256];    // h fp16
__device__ __align__(256) __half g_xmh[(size_t)NN_PAD * 64];    // xm fp16
__device__ __align__(256) __half g_w0h[256 * 256];
__device__ __align__(256) __half g_w1h[256 * 256];
__device__ __align__(256) __half g_w2h[256 * 64];

// ---------------- degrees / norms -------------------------------------------
__global__ void zero_init_kernel() {
    int i = blockIdx.x * blockDim.x + threadIdx.x;
    if (i < NN) { g_indeg[i] = 0; g_outdeg[i] = 0; g_fill[i] = 0; }
}

__global__ void degree_kernel(const int* __restrict__ src,
                              const int* __restrict__ dst, int nE) {
    int i = blockIdx.x * blockDim.x + threadIdx.x;
    if (i < nE) {
        atomicAdd(&g_outdeg[src[i]], 1);
        atomicAdd(&g_indeg[dst[i]], 1);
    }
}

__global__ void norm_kernel() {
    int i = blockIdx.x * blockDim.x + threadIdx.x;
    if (i < NN) {
        g_snorm[i] = rsqrtf(fmaxf((float)g_outdeg[i], 1.f));
        g_dnorm[i] = rsqrtf(fmaxf((float)g_indeg[i], 1.f));
    }
}

// ---------------- CSR build --------------------------------------------------
__global__ void scan1_kernel() {
    __shared__ int sh[SCAN_BS];
    int i = blockIdx.x * SCAN_BS + threadIdx.x;
    int v = (i < NN) ? g_indeg[i] : 0;
    sh[threadIdx.x] = v;
    __syncthreads();
    for (int off = 1; off < SCAN_BS; off <<= 1) {
        int t = (threadIdx.x >= off) ? sh[threadIdx.x - off] : 0;
        __syncthreads();
        sh[threadIdx.x] += t;
        __syncthreads();
    }
    if (i < NN) g_rowptr[i] = sh[threadIdx.x] - v;
    if (threadIdx.x == SCAN_BS - 1) g_blocksums[blockIdx.x] = sh[threadIdx.x];
}

__global__ void scan2_kernel(int nb) {
    __shared__ int sh[256];
    int t = threadIdx.x;
    int v = (t < nb) ? g_blocksums[t] : 0;
    sh[t] = v;
    __syncthreads();
    for (int off = 1; off < 256; off <<= 1) {
        int u = (t >= off) ? sh[t - off] : 0;
        __syncthreads();
        sh[t] += u;
        __syncthreads();
    }
    if (t < nb) g_blocksums[t] = sh[t] - v;
}

__global__ void scan3_kernel(int nE) {
    int i = blockIdx.x * SCAN_BS + threadIdx.x;
    if (i < NN) g_rowptr[i] += g_blocksums[blockIdx.x];
    if (i == 0) g_rowptr[NN] = nE;
}

__global__ void fillcsr_kernel(const int* __restrict__ src,
                               const int* __restrict__ dst, int nE) {
    int i = blockIdx.x * blockDim.x + threadIdx.x;
    if (i < nE) {
        int d = dst[i];
        int pos = g_rowptr[d] + atomicAdd(&g_fill[d], 1);
        g_esrc[pos] = src[i];
    }
}

// ---------------- fp32 -> fp16 convert ---------------------------------------
__global__ void convert_half_kernel(const float* __restrict__ in,
                                    __half* __restrict__ out, int n8) {
    int i = blockIdx.x * blockDim.x + threadIdx.x;
    if (i >= n8) return;
    float4 a = ((const float4*)in)[i * 2];
    float4 b = ((const float4*)in)[i * 2 + 1];
    __half2 h[4];
    h[0] = __floats2half2_rn(a.x, a.y);
    h[1] = __floats2half2_rn(a.z, a.w);
    h[2] = __floats2half2_rn(b.x, b.y);
    h[3] = __floats2half2_rn(b.z, b.w);
    ((uint4*)out)[i] = *(const uint4*)h;
}

// ---------------- gather256: fp16 in, fp32 accum, fp16 out -------------------
__global__ __launch_bounds__(256) void gather256h_kernel(
    const __half* __restrict__ x, __half* __restrict__ out) {
    int v = (blockIdx.x * blockDim.x + threadIdx.x) >> 5;
    int lane = threadIdx.x & 31;
    if (v >= NN) return;
    int row = g_rowptr[v];
    int end = g_rowptr[v + 1];
    float acc[8] = {0.f, 0.f, 0.f, 0.f, 0.f, 0.f, 0.f, 0.f};

    for (int base = row; base < end; base += 32) {
        int n = min(32, end - base);
        int s = 0;
        float w = 0.f;
        if (lane < n) { s = __ldg(&g_esrc[base + lane]); w = __ldg(&g_snorm[s]); }
        int k = 0;
        for (; k + 4 <= n; k += 4) {
            int s0 = __shfl_sync(0xffffffffu, s, k);
            int s1 = __shfl_sync(0xffffffffu, s, k + 1);
            int s2 = __shfl_sync(0xffffffffu, s, k + 2);
            int s3 = __shfl_sync(0xffffffffu, s, k + 3);
            float w0 = __shfl_sync(0xffffffffu, w, k);
            float w1 = __shfl_sync(0xffffffffu, w, k + 1);
            float w2 = __shfl_sync(0xffffffffu, w, k + 2);
            float w3 = __shfl_sync(0xffffffffu, w, k + 3);
            uint4 u0 = __ldg((const uint4*)(x + (size_t)s0 * 256) + lane);
            uint4 u1 = __ldg((const uint4*)(x + (size_t)s1 * 256) + lane);
            uint4 u2 = __ldg((const uint4*)(x + (size_t)s2 * 256) + lane);
            uint4 u3 = __ldg((const uint4*)(x + (size_t)s3 * 256) + lane);
            const __half2* p0 = (const __half2*)&u0;
            const __half2* p1 = (const __half2*)&u1;
            const __half2* p2 = (const __half2*)&u2;
            const __half2* p3 = (const __half2*)&u3;
#pragma unroll
            for (int j = 0; j < 4; j++) {
                float2 f0 = __half22float2(p0[j]);
                float2 f1 = __half22float2(p1[j]);
                float2 f2 = __half22float2(p2[j]);
                float2 f3 = __half22float2(p3[j]);
                acc[j * 2 + 0] += (w0 * f0.x + w1 * f1.x) + (w2 * f2.x + w3 * f3.x);
                acc[j * 2 + 1] += (w0 * f0.y + w1 * f1.y) + (w2 * f2.y + w3 * f3.y);
            }
        }
        for (; k < n; k++) {
            int s0 = __shfl_sync(0xffffffffu, s, k);
            float w0 = __shfl_sync(0xffffffffu, w, k);
            uint4 u0 = __ldg((const uint4*)(x + (size_t)s0 * 256) + lane);
            const __half2* p0 = (const __half2*)&u0;
#pragma unroll
            for (int j = 0; j < 4; j++) {
                float2 f0 = __half22float2(p0[j]);
                acc[j * 2 + 0] += w0 * f0.x;
                acc[j * 2 + 1] += w0 * f0.y;
            }
        }
    }
    __half2 hv[4];
#pragma unroll
    for (int j = 0; j < 4; j++)
        hv[j] = __floats2half2_rn(acc[j * 2], acc[j * 2 + 1]);
    ((uint4*)(out + (size_t)v * 256))[lane] = *(const uint4*)hv;
}

// ---------------- gather64: fp16 in, fp32 out --------------------------------
__global__ __launch_bounds__(256) void gather64h_kernel(
    const __half* __restrict__ x, float* __restrict__ out) {
    int v = (blockIdx.x * blockDim.x + threadIdx.x) >> 5;
    int lane = threadIdx.x & 31;
    if (v >= NN) return;
    int row = g_rowptr[v];
    int end = g_rowptr[v + 1];
    float2 acc = make_float2(0.f, 0.f);
    for (int base = row; base < end; base += 32) {
        int n = min(32, end - base);
        int s = 0;
        if (lane < n) s = __ldg(&g_esrc[base + lane]);
        int k = 0;
        for (; k + 4 <= n; k += 4) {
            int s0 = __shfl_sync(0xffffffffu, s, k);
            int s1 = __shfl_sync(0xffffffffu, s, k + 1);
            int s2 = __shfl_sync(0xffffffffu, s, k + 2);
            int s3 = __shfl_sync(0xffffffffu, s, k + 3);
            __half2 a0 = __ldg((const __half2*)(x + (size_t)s0 * 64) + lane);
            __half2 a1 = __ldg((const __half2*)(x + (size_t)s1 * 64) + lane);
            __half2 a2 = __ldg((const __half2*)(x + (size_t)s2 * 64) + lane);
            __half2 a3 = __ldg((const __half2*)(x + (size_t)s3 * 64) + lane);
            float2 f0 = __half22float2(a0);
            float2 f1 = __half22float2(a1);
            float2 f2 = __half22float2(a2);
            float2 f3 = __half22float2(a3);
            acc.x += (f0.x + f1.x) + (f2.x + f3.x);
            acc.y += (f0.y + f1.y) + (f2.y + f3.y);
        }
        for (; k < n; k++) {
            int s0 = __shfl_sync(0xffffffffu, s, k);
            float2 f0 = __half22float2(__ldg((const __half2*)(x + (size_t)s0 * 64) + lane));
            acc.x += f0.x;
            acc.y += f0.y;
        }
    }
    float w = g_dnorm[v];
    ((float2*)(out + (size_t)v * 64))[lane] = make_float2(acc.x * w, acc.y * w);
}

// ---------------- fp16 tensor-core GEMM --------------------------------------
// C = act( (A * norm[:,None]) @ W ),  A,W,C fp16, accum fp32, K=256.
// BM=128, BK=32 (2 x k16 steps). BN=128: warp tile 64x32; BN=64: 32x32.
template <int BN, bool RELU>
__global__ __launch_bounds__(256, 2) void gemm_h_kernel(
    const __half* __restrict__ A, const __half* __restrict__ Wh,
    const float* __restrict__ norm, __half* __restrict__ C, int M, int N) {
    constexpr int BM = 128, BK = 32;
    constexpr int WM = (BN == 128) ? 64 : 32;   // warp-tile rows
    constexpr int FM = WM / 16;                 // A frags
    constexpr int BQ = (BN == 128) ? 2 : 1;     // uint4s per thread for B tile
    __shared__ __half As[BM][BK + 8];           // 10 KB
    __shared__ __half Bs[BK][BN + 8];           // 8.5 / 4.5 KB
    __shared__ float  stage[8][16 * 24];        // 12 KB epilogue staging

    const int t = threadIdx.x;
    const int warp = t >> 5;
    const int lane = t & 31;
    const int wm = (BN == 128) ? (warp >> 2) : (warp >> 1);
    const int wn = (BN == 128) ? (warp & 3) : (warp & 1);
    const int row0 = blockIdx.x * BM;
    const int col0 = blockIdx.y * BN;

    // A tile: 128 rows x 32 halves; thread t -> row t>>1, 16 halves at (t&1)*16
    const int a_row = t >> 1;
    const int a_c0 = (t & 1) * 16;
    const bool a_ok = (row0 + a_row) < M;
    const float nrmf = a_ok ? __ldg(&norm[row0 + a_row]) : 0.f;
    const __half2 nrm2 = __float2half2_rn(nrmf);
    const __half* Aptr = A + (size_t)(row0 + a_row) * 256 + a_c0;

    // B tile: 32 rows x BN halves; thread t -> row t>>3, BQ uint4 at (t&7)*8*BQ
    const int b_row = t >> 3;
    const int b_c0 = (t & 7) * 8 * BQ;

    wmma::fragment<wmma::accumulator, 16, 16, 16, float> acc[FM][2];
#pragma unroll
    for (int i = 0; i < FM; i++)
#pragma unroll
        for (int j = 0; j < 2; j++) wmma::fill_fragment(acc[i][j], 0.f);

    uint4 ar[2], br[BQ];
#pragma unroll
    for (int q = 0; q < 2; q++) ar[q] = *(const uint4*)(Aptr + q * 8);
#pragma unroll
    for (int q = 0; q < BQ; q++)
        br[q] = *(const uint4*)&Wh[(size_t)b_row * N + col0 + b_c0 + q * 8];

    auto store_tiles = [&]() {
#pragma unroll
        for (int q = 0; q < 2; q++) {
            const __half2* p = (const __half2*)&ar[q];
            __half2* dstp = (__half2*)&As[a_row][a_c0 + q * 8];
#pragma unroll
            for (int j = 0; j < 4; j++) dstp[j] = __hmul2(p[j], nrm2);
        }
#pragma unroll
        for (int q = 0; q < BQ; q++)
            *(uint4*)&Bs[b_row][b_c0 + q * 8] = br[q];
    };

    store_tiles();
    __syncthreads();

    for (int k0 = 0; k0 < 256; k0 += BK) {
        const bool has_next = (k0 + BK) < 256;
        if (has_next) {
#pragma unroll
            for (int q = 0; q < 2; q++)
                ar[q] = *(const uint4*)(Aptr + k0 + BK + q * 8);
#pragma unroll
            for (int q = 0; q < BQ; q++)
                br[q] = *(const uint4*)&Wh[(size_t)(k0 + BK + b_row) * N + col0 + b_c0 + q * 8];
        }
#pragma unroll
        for (int kk = 0; kk < BK; kk += 16) {
            wmma::fragment<wmma::matrix_a, 16, 16, 16, __half, wmma::row_major> af[FM];
            wmma::fragment<wmma::matrix_b, 16, 16, 16, __half, wmma::row_major> bf[2];
#pragma unroll
            for (int i = 0; i < FM; i++)
                wmma::load_matrix_sync(af[i], &As[wm * WM + i * 16][kk], BK + 8);
#pragma unroll
            for (int j = 0; j < 2; j++)
                wmma::load_matrix_sync(bf[j], &Bs[kk][wn * 32 + j * 16], BN + 8);
#pragma unroll
            for (int i = 0; i < FM; i++)
#pragma unroll
                for (int j = 0; j < 2; j++)
                    wmma::mma_sync(acc[i][j], af[i], bf[j], acc[i][j]);
        }
        __syncthreads();
        if (has_next) {
            store_tiles();
            __syncthreads();
        }
    }

    // epilogue: float frag -> warp staging -> fp16 global
#pragma unroll
    for (int i = 0; i < FM; i++)
#pragma unroll
        for (int j = 0; j < 2; j++) {
            if (RELU) {
#pragma unroll
                for (int e = 0; e < acc[i][j].num_elements; e++)
                    acc[i][j].x[e] = fmaxf(acc[i][j].x[e], 0.f);
            }
            wmma::store_matrix_sync(&stage[warp][0], acc[i][j], 24,
                                    wmma::mem_row_major);
            __syncwarp();
            int r = lane >> 1;
            int ch = (lane & 1) * 8;
            const float* sp = &stage[warp][r * 24 + ch];
            __half2 hv[4];
#pragma unroll
            for (int q = 0; q < 4; q++)
                hv[q] = __floats2half2_rn(sp[q * 2], sp[q * 2 + 1]);
            __half* cp = C + (size_t)(row0 + wm * WM + i * 16 + r) * N +
                         col0 + wn * 32 + j * 16 + ch;
            *(uint4*)cp = *(const uint4*)hv;
            __syncwarp();
        }
}

// ---------------- launch -----------------------------------------------------
extern "C" void kernel_launch(void* const* d_in, const int* in_sizes, int n_in,
                              void* d_out, int out_size) {
    const float* feat = (const float*)d_in[0];
    const int* src = (const int*)d_in[1];
    const int* dst = (const int*)d_in[2];
    const float* W0 = (const float*)d_in[3];
    const float* W1 = (const float*)d_in[4];
    const float* W2 = (const float*)d_in[5];
    float* out = (float*)d_out;
    const int nE = in_sizes[1];

    __half *xh, *aggh, *hh, *xmh, *w0h, *w1h, *w2h;
    float *snorm, *dnorm;
    cudaGetSymbolAddress((void**)&xh, g_xh);
    cudaGetSymbolAddress((void**)&aggh, g_aggh);
    cudaGetSymbolAddress((void**)&hh, g_hh);
    cudaGetSymbolAddress((void**)&xmh, g_xmh);
    cudaGetSymbolAddress((void**)&w0h, g_w0h);
    cudaGetSymbolAddress((void**)&w1h, g_w1h);
    cudaGetSymbolAddress((void**)&w2h, g_w2h);
    cudaGetSymbolAddress((void**)&snorm, g_snorm);
    cudaGetSymbolAddress((void**)&dnorm, g_dnorm);

    const int T = 256;
    const int NB = (NN + SCAN_BS - 1) / SCAN_BS;      // 196
    const int gemm_rows = NN_PAD / 128;               // 782
    const int gather_blocks = (NN * 32 + T - 1) / T;  // 12500
    const int conv8 = NN * 256 / 8;

    // degrees + norms + CSR build
    zero_init_kernel<<<(NN + T - 1) / T, T>>>();
    degree_kernel<<<(nE + T - 1) / T, T>>>(src, dst, nE);
    norm_kernel<<<(NN + T - 1) / T, T>>>();
    scan1_kernel<<<NB, SCAN_BS>>>();
    scan2_kernel<<<1, 256>>>(NB);
    scan3_kernel<<<NB, SCAN_BS>>>(nE);
    fillcsr_kernel<<<(nE + T - 1) / T, T>>>(src, dst, nE);

    // weight + feat conversion (fp32 -> fp16)
    convert_half_kernel<<<(conv8 + T - 1) / T, T>>>(feat, xh, conv8);
    convert_half_kernel<<<(256 * 256 / 8 + T - 1) / T, T>>>(W0, w0h, 256 * 256 / 8);
    convert_half_kernel<<<(256 * 256 / 8 + T - 1) / T, T>>>(W1, w1h, 256 * 256 / 8);
    convert_half_kernel<<<(256 * 64 / 8 + T - 1) / T, T>>>(W2, w2h, 256 * 64 / 8);

    // layer 0: aggh = A^T (xh * snorm); hh = relu((aggh * dnorm) @ W0)
    gather256h_kernel<<<gather_blocks, T>>>(xh, aggh);
    gemm_h_kernel<128, true><<<dim3(gemm_rows, 2), T>>>(aggh, w0h, dnorm, hh, NN, 256);

    // layer 1
    gather256h_kernel<<<gather_blocks, T>>>(hh, aggh);
    gemm_h_kernel<128, true><<<dim3(gemm_rows, 2), T>>>(aggh, w1h, dnorm, hh, NN, 256);

    // layer 2: xmh = (hh * snorm) @ W2; out = dnorm * (A^T xmh)
    gemm_h_kernel<64, false><<<dim3(gemm_rows, 1), T>>>(hh, w2h, snorm, xmh, NN, 64);
    gather64h_kernel<<<gather_blocks, T>>>(xmh, out);
}

// round 9
// speedup vs baseline: 3.8036x; 1.0112x over previous
#include <cuda_runtime.h>
#include <cuda_fp16.h>
#include <mma.h>
#include <cstdint>

using namespace nvcuda;

#define NN 100000
#define NN_PAD 100096   // 782 * 128
#define MAXE 3300000
#define SCAN_BS 512

// ---------------- scratch (static device globals; zero-initialized) ---------
__device__ __align__(256) int    g_indeg[NN];
__device__ __align__(256) int    g_outdeg[NN];
__device__ __align__(256) int    g_fill[NN];
__device__ __align__(256) int    g_rowptr[NN + 1];
__device__ __align__(256) int    g_blocksums[256];
__device__ __align__(256) int    g_esrc[MAXE];
__device__ __align__(256) float  g_snorm[NN];
__device__ __align__(256) float  g_dnorm[NN];
__device__ __align__(256) __half g_xh[(size_t)NN_PAD * 256];    // feat fp16
__device__ __align__(256) __half g_aggh[(size_t)NN_PAD * 256];  // agg fp16
__device__ __align__(256) __half g_hh[(size_t)NN_PAD * 256];    // h fp16
__device__ __align__(256) __half g_xmh[(size_t)NN_PAD * 64];    // xm fp16
__device__ __align__(256) __half g_w0h[256 * 256];
__device__ __align__(256) __half g_w1h[256 * 256];
__device__ __align__(256) __half g_w2h[256 * 64];

// ---------------- degrees --------------------------------------------------
__global__ void zero_init_kernel() {
    int i = blockIdx.x * blockDim.x + threadIdx.x;
    if (i < NN) { g_indeg[i] = 0; g_outdeg[i] = 0; }
}

__global__ void degree_kernel(const int* __restrict__ src,
                              const int* __restrict__ dst, int nE) {
    int i = blockIdx.x * blockDim.x + threadIdx.x;
    if (i < nE) {
        atomicAdd(&g_outdeg[src[i]], 1);
        atomicAdd(&g_indeg[dst[i]], 1);
    }
}

// ---------------- CSR build (norms fused into scan3) -------------------------
__global__ void scan1_kernel() {
    __shared__ int sh[SCAN_BS];
    int i = blockIdx.x * SCAN_BS + threadIdx.x;
    int v = (i < NN) ? g_indeg[i] : 0;
    sh[threadIdx.x] = v;
    __syncthreads();
    for (int off = 1; off < SCAN_BS; off <<= 1) {
        int t = (threadIdx.x >= off) ? sh[threadIdx.x - off] : 0;
        __syncthreads();
        sh[threadIdx.x] += t;
        __syncthreads();
    }
    if (i < NN) g_rowptr[i] = sh[threadIdx.x] - v;
    if (threadIdx.x == SCAN_BS - 1) g_blocksums[blockIdx.x] = sh[threadIdx.x];
}

__global__ void scan2_kernel(int nb) {
    __shared__ int sh[256];
    int t = threadIdx.x;
    int v = (t < nb) ? g_blocksums[t] : 0;
    sh[t] = v;
    __syncthreads();
    for (int off = 1; off < 256; off <<= 1) {
        int u = (t >= off) ? sh[t - off] : 0;
        __syncthreads();
        sh[t] += u;
        __syncthreads();
    }
    if (t < nb) g_blocksums[t] = sh[t] - v;
}

// finalizes rowptr, seeds fill counters, computes both norms
__global__ void scan3_kernel(int nE) {
    int i = blockIdx.x * SCAN_BS + threadIdx.x;
    if (i < NN) {
        int rp = g_rowptr[i] + g_blocksums[blockIdx.x];
        g_rowptr[i] = rp;
        g_fill[i] = rp;
        g_snorm[i] = rsqrtf(fmaxf((float)g_outdeg[i], 1.f));
        g_dnorm[i] = rsqrtf(fmaxf((float)g_indeg[i], 1.f));
    }
    if (i == 0) g_rowptr[NN] = nE;
}

__global__ void fillcsr_kernel(const int* __restrict__ src,
                               const int* __restrict__ dst, int nE) {
    int i = blockIdx.x * blockDim.x + threadIdx.x;
    if (i < nE) {
        int pos = atomicAdd(&g_fill[dst[i]], 1);
        g_esrc[pos] = src[i];
    }
}

// ---------------- fp32 -> fp16 convert ---------------------------------------
__global__ void convert_half_kernel(const float* __restrict__ in,
                                    __half* __restrict__ out, int n8) {
    int i = blockIdx.x * blockDim.x + threadIdx.x;
    if (i >= n8) return;
    float4 a = ((const float4*)in)[i * 2];
    float4 b = ((const float4*)in)[i * 2 + 1];
    __half2 h[4];
    h[0] = __floats2half2_rn(a.x, a.y);
    h[1] = __floats2half2_rn(a.z, a.w);
    h[2] = __floats2half2_rn(b.x, b.y);
    h[3] = __floats2half2_rn(b.z, b.w);
    ((uint4*)out)[i] = *(const uint4*)h;
}

// ---------------- gather256: fp16 in, fp32 accum, fp16 out -------------------
__global__ __launch_bounds__(256) void gather256h_kernel(
    const __half* __restrict__ x, __half* __restrict__ out) {
    int v = (blockIdx.x * blockDim.x + threadIdx.x) >> 5;
    int lane = threadIdx.x & 31;
    if (v >= NN) return;
    int row = g_rowptr[v];
    int end = g_rowptr[v + 1];
    float acc[8] = {0.f, 0.f, 0.f, 0.f, 0.f, 0.f, 0.f, 0.f};

    for (int base = row; base < end; base += 32) {
        int n = min(32, end - base);
        int s = 0;
        float w = 0.f;
        if (lane < n) { s = __ldg(&g_esrc[base + lane]); w = __ldg(&g_snorm[s]); }
        int k = 0;
        for (; k + 4 <= n; k += 4) {
            int s0 = __shfl_sync(0xffffffffu, s, k);
            int s1 = __shfl_sync(0xffffffffu, s, k + 1);
            int s2 = __shfl_sync(0xffffffffu, s, k + 2);
            int s3 = __shfl_sync(0xffffffffu, s, k + 3);
            float w0 = __shfl_sync(0xffffffffu, w, k);
            float w1 = __shfl_sync(0xffffffffu, w, k + 1);
            float w2 = __shfl_sync(0xffffffffu, w, k + 2);
            float w3 = __shfl_sync(0xffffffffu, w, k + 3);
            uint4 u0 = __ldg((const uint4*)(x + (size_t)s0 * 256) + lane);
            uint4 u1 = __ldg((const uint4*)(x + (size_t)s1 * 256) + lane);
            uint4 u2 = __ldg((const uint4*)(x + (size_t)s2 * 256) + lane);
            uint4 u3 = __ldg((const uint4*)(x + (size_t)s3 * 256) + lane);
            const __half2* p0 = (const __half2*)&u0;
            const __half2* p1 = (const __half2*)&u1;
            const __half2* p2 = (const __half2*)&u2;
            const __half2* p3 = (const __half2*)&u3;
#pragma unroll
            for (int j = 0; j < 4; j++) {
                float2 f0 = __half22float2(p0[j]);
                float2 f1 = __half22float2(p1[j]);
                float2 f2 = __half22float2(p2[j]);
                float2 f3 = __half22float2(p3[j]);
                acc[j * 2 + 0] += (w0 * f0.x + w1 * f1.x) + (w2 * f2.x + w3 * f3.x);
                acc[j * 2 + 1] += (w0 * f0.y + w1 * f1.y) + (w2 * f2.y + w3 * f3.y);
            }
        }
        for (; k < n; k++) {
            int s0 = __shfl_sync(0xffffffffu, s, k);
            float w0 = __shfl_sync(0xffffffffu, w, k);
            uint4 u0 = __ldg((const uint4*)(x + (size_t)s0 * 256) + lane);
            const __half2* p0 = (const __half2*)&u0;
#pragma unroll
            for (int j = 0; j < 4; j++) {
                float2 f0 = __half22float2(p0[j]);
                acc[j * 2 + 0] += w0 * f0.x;
                acc[j * 2 + 1] += w0 * f0.y;
            }
        }
    }
    __half2 hv[4];
#pragma unroll
    for (int j = 0; j < 4; j++)
        hv[j] = __floats2half2_rn(acc[j * 2], acc[j * 2 + 1]);
    ((uint4*)(out + (size_t)v * 256))[lane] = *(const uint4*)hv;
}

// ---------------- gather64: fp16 in, fp32 out --------------------------------
__global__ __launch_bounds__(256) void gather64h_kernel(
    const __half* __restrict__ x, float* __restrict__ out) {
    int v = (blockIdx.x * blockDim.x + threadIdx.x) >> 5;
    int lane = threadIdx.x & 31;
    if (v >= NN) return;
    int row = g_rowptr[v];
    int end = g_rowptr[v + 1];
    float2 acc = make_float2(0.f, 0.f);
    for (int base = row; base < end; base += 32) {
        int n = min(32, end - base);
        int s = 0;
        if (lane < n) s = __ldg(&g_esrc[base + lane]);
        int k = 0;
        for (; k + 4 <= n; k += 4) {
            int s0 = __shfl_sync(0xffffffffu, s, k);
            int s1 = __shfl_sync(0xffffffffu, s, k + 1);
            int s2 = __shfl_sync(0xffffffffu, s, k + 2);
            int s3 = __shfl_sync(0xffffffffu, s, k + 3);
            __half2 a0 = __ldg((const __half2*)(x + (size_t)s0 * 64) + lane);
            __half2 a1 = __ldg((const __half2*)(x + (size_t)s1 * 64) + lane);
            __half2 a2 = __ldg((const __half2*)(x + (size_t)s2 * 64) + lane);
            __half2 a3 = __ldg((const __half2*)(x + (size_t)s3 * 64) + lane);
            float2 f0 = __half22float2(a0);
            float2 f1 = __half22float2(a1);
            float2 f2 = __half22float2(a2);
            float2 f3 = __half22float2(a3);
            acc.x += (f0.x + f1.x) + (f2.x + f3.x);
            acc.y += (f0.y + f1.y) + (f2.y + f3.y);
        }
        for (; k < n; k++) {
            int s0 = __shfl_sync(0xffffffffu, s, k);
            float2 f0 = __half22float2(__ldg((const __half2*)(x + (size_t)s0 * 64) + lane));
            acc.x += f0.x;
            acc.y += f0.y;
        }
    }
    float w = g_dnorm[v];
    ((float2*)(out + (size_t)v * 64))[lane] = make_float2(acc.x * w, acc.y * w);
}

// ---------------- fp16 tensor-core GEMM, BK=64 -------------------------------
// C = act( (A * norm[:,None]) @ W ),  A,W,C fp16, accum fp32, K=256.
// BM=128, BK=64 (4 x k16 per tile, only 4 barrier pairs total).
// BN=128: warp tile 64x32; BN=64: 32x32.
template <int BN, bool RELU>
__global__ __launch_bounds__(256, 2) void gemm_h_kernel(
    const __half* __restrict__ A, const __half* __restrict__ Wh,
    const float* __restrict__ norm, __half* __restrict__ C, int M, int N) {
    constexpr int BM = 128, BK = 64;
    constexpr int WM = (BN == 128) ? 64 : 32;   // warp-tile rows
    constexpr int FM = WM / 16;                 // A frags
    constexpr int BQ = (BN == 128) ? 4 : 2;     // uint4 per thread for B tile
    __shared__ __half As[BM][BK + 8];           // 128*72*2 = 18.4 KB
    __shared__ __half Bs[BK][BN + 8];           // 64*136*2 = 17.4 / 9.2 KB
    __shared__ float  stage[8][16 * 24];        // 12 KB epilogue staging

    const int t = threadIdx.x;
    const int warp = t >> 5;
    const int lane = t & 31;
    const int wm = (BN == 128) ? (warp >> 2) : (warp >> 1);
    const int wn = (BN == 128) ? (warp & 3) : (warp & 1);
    const int row0 = blockIdx.x * BM;
    const int col0 = blockIdx.y * BN;

    // A tile: 128 rows x 64 halves; thread t -> row t>>1, 4 uint4 at (t&1)*32
    const int a_row = t >> 1;
    const int a_c0 = (t & 1) * 32;
    const bool a_ok = (row0 + a_row) < M;
    const float nrmf = a_ok ? __ldg(&norm[row0 + a_row]) : 0.f;
    const __half2 nrm2 = __float2half2_rn(nrmf);
    const __half* Aptr = A + (size_t)(row0 + a_row) * 256 + a_c0;

    // B tile: 64 rows x BN halves; thread t -> row t>>2, BQ uint4 at (t&3)*8*BQ
    const int b_row = t >> 2;
    const int b_c0 = (t & 3) * 8 * BQ;

    wmma::fragment<wmma::accumulator, 16, 16, 16, float> acc[FM][2];
#pragma unroll
    for (int i = 0; i < FM; i++)
#pragma unroll
        for (int j = 0; j < 2; j++) wmma::fill_fragment(acc[i][j], 0.f);

    uint4 ar[4], br[BQ];
#pragma unroll
    for (int q = 0; q < 4; q++) ar[q] = *(const uint4*)(Aptr + q * 8);
#pragma unroll
    for (int q = 0; q < BQ; q++)
        br[q] = *(const uint4*)&Wh[(size_t)b_row * N + col0 + b_c0 + q * 8];

    auto store_tiles = [&]() {
#pragma unroll
        for (int q = 0; q < 4; q++) {
            const __half2* p = (const __half2*)&ar[q];
            __half2* dstp = (__half2*)&As[a_row][a_c0 + q * 8];
#pragma unroll
            for (int j = 0; j < 4; j++) dstp[j] = __hmul2(p[j], nrm2);
        }
#pragma unroll
        for (int q = 0; q < BQ; q++)
            *(uint4*)&Bs[b_row][b_c0 + q * 8] = br[q];
    };

    store_tiles();
    __syncthreads();

    for (int k0 = 0; k0 < 256; k0 += BK) {
        const bool has_next = (k0 + BK) < 256;
        if (has_next) {
#pragma unroll
            for (int q = 0; q < 4; q++)
                ar[q] = *(const uint4*)(Aptr + k0 + BK + q * 8);
#pragma unroll
            for (int q = 0; q < BQ; q++)
                br[q] = *(const uint4*)&Wh[(size_t)(k0 + BK + b_row) * N + col0 + b_c0 + q * 8];
        }
#pragma unroll
        for (int kk = 0; kk < BK; kk += 16) {
            wmma::fragment<wmma::matrix_a, 16, 16, 16, __half, wmma::row_major> af[FM];
            wmma::fragment<wmma::matrix_b, 16, 16, 16, __half, wmma::row_major> bf[2];
#pragma unroll
            for (int i = 0; i < FM; i++)
                wmma::load_matrix_sync(af[i], &As[wm * WM + i * 16][kk], BK + 8);
#pragma unroll
            for (int j = 0; j < 2; j++)
                wmma::load_matrix_sync(bf[j], &Bs[kk][wn * 32 + j * 16], BN + 8);
#pragma unroll
            for (int i = 0; i < FM; i++)
#pragma unroll
                for (int j = 0; j < 2; j++)
                    wmma::mma_sync(acc[i][j], af[i], bf[j], acc[i][j]);
        }
        __syncthreads();
        if (has_next) {
            store_tiles();
            __syncthreads();
        }
    }

    // epilogue: float frag -> warp staging -> fp16 global
#pragma unroll
    for (int i = 0; i < FM; i++)
#pragma unroll
        for (int j = 0; j < 2; j++) {
            if (RELU) {
#pragma unroll
                for (int e = 0; e < acc[i][j].num_elements; e++)
                    acc[i][j].x[e] = fmaxf(acc[i][j].x[e], 0.f);
            }
            wmma::store_matrix_sync(&stage[warp][0], acc[i][j], 24,
                                    wmma::mem_row_major);
            __syncwarp();
            int r = lane >> 1;
            int ch = (lane & 1) * 8;
            const float* sp = &stage[warp][r * 24 + ch];
            __half2 hv[4];
#pragma unroll
            for (int q = 0; q < 4; q++)
                hv[q] = __floats2half2_rn(sp[q * 2], sp[q * 2 + 1]);
            __half* cp = C + (size_t)(row0 + wm * WM + i * 16 + r) * N +
                         col0 + wn * 32 + j * 16 + ch;
            *(uint4*)cp = *(const uint4*)hv;
            __syncwarp();
        }
}

// ---------------- launch -----------------------------------------------------
extern "C" void kernel_launch(void* const* d_in, const int* in_sizes, int n_in,
                              void* d_out, int out_size) {
    const float* feat = (const float*)d_in[0];
    const int* src = (const int*)d_in[1];
    const int* dst = (const int*)d_in[2];
    const float* W0 = (const float*)d_in[3];
    const float* W1 = (const float*)d_in[4];
    const float* W2 = (const float*)d_in[5];
    float* out = (float*)d_out;
    const int nE = in_sizes[1];

    __half *xh, *aggh, *hh, *xmh, *w0h, *w1h, *w2h;
    float *snorm, *dnorm;
    cudaGetSymbolAddress((void**)&xh, g_xh);
    cudaGetSymbolAddress((void**)&aggh, g_aggh);
    cudaGetSymbolAddress((void**)&hh, g_hh);
    cudaGetSymbolAddress((void**)&xmh, g_xmh);
    cudaGetSymbolAddress((void**)&w0h, g_w0h);
    cudaGetSymbolAddress((void**)&w1h, g_w1h);
    cudaGetSymbolAddress((void**)&w2h, g_w2h);
    cudaGetSymbolAddress((void**)&snorm, g_snorm);
    cudaGetSymbolAddress((void**)&dnorm, g_dnorm);

    const int T = 256;
    const int NB = (NN + SCAN_BS - 1) / SCAN_BS;      // 196
    const int gemm_rows = NN_PAD / 128;               // 782
    const int gather_blocks = (NN * 32 + T - 1) / T;  // 12500
    const int conv8 = NN * 256 / 8;

    // degrees + CSR build (norms fused into scan3)
    zero_init_kernel<<<(NN + T - 1) / T, T>>>();
    degree_kernel<<<(nE + T - 1) / T, T>>>(src, dst, nE);
    scan1_kernel<<<NB, SCAN_BS>>>();
    scan2_kernel<<<1, 256>>>(NB);
    scan3_kernel<<<NB, SCAN_BS>>>(nE);
    fillcsr_kernel<<<(nE + T - 1) / T, T>>>(src, dst, nE);

    // weight + feat conversion (fp32 -> fp16)
    convert_half_kernel<<<(conv8 + T - 1) / T, T>>>(feat, xh, conv8);
    convert_half_kernel<<<(256 * 256 / 8 + T - 1) / T, T>>>(W0, w0h, 256 * 256 / 8);
    convert_half_kernel<<<(256 * 256 / 8 + T - 1) / T, T>>>(W1, w1h, 256 * 256 / 8);
    convert_half_kernel<<<(256 * 64 / 8 + T - 1) / T, T>>>(W2, w2h, 256 * 64 / 8);

    // layer 0: aggh = A^T (xh * snorm); hh = relu((aggh * dnorm) @ W0)
    gather256h_kernel<<<gather_blocks, T>>>(xh, aggh);
    gemm_h_kernel<128, true><<<dim3(gemm_rows, 2), T>>>(aggh, w0h, dnorm, hh, NN, 256);

    // layer 1
    gather256h_kernel<<<gather_blocks, T>>>(hh, aggh);
    gemm_h_kernel<128, true><<<dim3(gemm_rows, 2), T>>>(aggh, w1h, dnorm, hh, NN, 256);

    // layer 2: xmh = (hh * snorm) @ W2; out = dnorm * (A^T xmh)
    gemm_h_kernel<64, false><<<dim3(gemm_rows, 1), T>>>(hh, w2h, snorm, xmh, NN, 64);
    gather64h_kernel<<<gather_blocks, T>>>(xmh, out);
}